// round 3
// baseline (speedup 1.0000x reference)
#include <cuda_runtime.h>
#include <cstdint>
#include <math_constants.h>

#define B_DIM 4
#define T_DIM 4096
#define C_DIM 512
#define ATTN_SCALE 0.044194173824159216f  // 1/sqrt(512)

// Scratch for projected Q/K/V (fp32 values pre-rounded to tf32 precision).
__device__ float g_Qp[B_DIM * T_DIM * C_DIM];
__device__ float g_Kp[B_DIM * T_DIM * C_DIM];
__device__ float g_Vp[B_DIM * T_DIM * C_DIM];

__device__ __forceinline__ uint32_t f2tf(float x) {
    uint32_t u;
    asm("cvt.rna.tf32.f32 %0, %1;" : "=r"(u) : "f"(x));
    return u;
}

__device__ __forceinline__ void cp16(void* s, const void* g) {
    uint32_t sa = (uint32_t)__cvta_generic_to_shared(s);
    asm volatile("cp.async.cg.shared.global [%0], [%1], 16;" :: "r"(sa), "l"(g));
}
#define CP_COMMIT asm volatile("cp.async.commit_group;")
#define CP_WAIT(N) asm volatile("cp.async.wait_group %0;" :: "n"(N))

#define MMA_TF32(d, a0, a1, a2, a3, b0, b1)                                  \
    asm volatile(                                                            \
        "mma.sync.aligned.m16n8k8.row.col.f32.tf32.tf32.f32 "                \
        "{%0,%1,%2,%3},{%4,%5,%6,%7},{%8,%9},{%0,%1,%2,%3};"                 \
        : "+f"((d)[0]), "+f"((d)[1]), "+f"((d)[2]), "+f"((d)[3])             \
        : "r"(a0), "r"(a1), "r"(a2), "r"(a3), "r"(b0), "r"(b1))

// ============================================================================
// Projection GEMM: out[M,N] = x[M,K] @ W[K,N] + b,  M=16384, K=N=512.
// Outputs PRE-ROUNDED to tf32 so the attention mainloop needs no CVTs.
// ============================================================================
__global__ __launch_bounds__(256) void proj_kernel(
    const float* __restrict__ xq, const float* __restrict__ xk, const float* __restrict__ xv,
    const float* __restrict__ Wq, const float* __restrict__ bq,
    const float* __restrict__ Wk, const float* __restrict__ bk,
    const float* __restrict__ Wv, const float* __restrict__ bv)
{
    __shared__ float As[2][128][20];
    __shared__ float Bs[2][16][68];

    const int which = blockIdx.z;
    const float* x    = (which == 0) ? xq : (which == 1) ? xk : xv;
    const float* W    = (which == 0) ? Wq : (which == 1) ? Wk : Wv;
    const float* bias = (which == 0) ? bq : (which == 1) ? bk : bv;
    float* out        = (which == 0) ? g_Qp : (which == 1) ? g_Kp : g_Vp;

    const int m0 = blockIdx.x * 128;
    const int n0 = blockIdx.y * 64;
    const int tid = threadIdx.x, lane = tid & 31, wid = tid >> 5;
    const int wr = wid >> 1, wc = wid & 1;

    float acc[2][4][4];
#pragma unroll
    for (int a = 0; a < 2; a++)
#pragma unroll
        for (int b = 0; b < 4; b++)
#pragma unroll
            for (int c = 0; c < 4; c++) acc[a][b][c] = 0.f;

    auto issue = [&](int buf, int k0) {
#pragma unroll
        for (int j = 0; j < 2; j++) {
            int i = tid + 256 * j;
            int row = i >> 2, cf = i & 3;
            cp16(&As[buf][row][cf * 4], x + (size_t)(m0 + row) * C_DIM + k0 + cf * 4);
        }
        {
            int row = tid >> 4, cf = tid & 15;
            cp16(&Bs[buf][row][cf * 4], W + (size_t)(k0 + row) * C_DIM + n0 + cf * 4);
        }
        CP_COMMIT;
    };

    issue(0, 0);
    for (int kt = 0; kt < 32; ++kt) {
        if (kt + 1 < 32) { issue((kt + 1) & 1, (kt + 1) * 16); CP_WAIT(1); }
        else             { CP_WAIT(0); }
        __syncthreads();
        const int buf = kt & 1;
#pragma unroll
        for (int ks = 0; ks < 2; ++ks) {
            uint32_t afr[2][4];
#pragma unroll
            for (int mt = 0; mt < 2; ++mt) {
                int r = wr * 32 + mt * 16 + (lane >> 2);
                int cc = ks * 8 + (lane & 3);
                afr[mt][0] = f2tf(As[buf][r][cc]);
                afr[mt][1] = f2tf(As[buf][r + 8][cc]);
                afr[mt][2] = f2tf(As[buf][r][cc + 4]);
                afr[mt][3] = f2tf(As[buf][r + 8][cc + 4]);
            }
#pragma unroll
            for (int nt = 0; nt < 4; ++nt) {
                int n = wc * 32 + nt * 8 + (lane >> 2);
                int kk = ks * 8 + (lane & 3);
                uint32_t b0 = f2tf(Bs[buf][kk][n]);
                uint32_t b1 = f2tf(Bs[buf][kk + 4][n]);
                MMA_TF32(acc[0][nt], afr[0][0], afr[0][1], afr[0][2], afr[0][3], b0, b1);
                MMA_TF32(acc[1][nt], afr[1][0], afr[1][1], afr[1][2], afr[1][3], b0, b1);
            }
        }
        __syncthreads();
    }

#pragma unroll
    for (int mt = 0; mt < 2; ++mt) {
        int row = m0 + wr * 32 + mt * 16 + (lane >> 2);
#pragma unroll
        for (int nt = 0; nt < 4; ++nt) {
            int col = n0 + wc * 32 + nt * 8 + 2 * (lane & 3);
            float2 bb = *(const float2*)&bias[col];
            float2 v0 = make_float2(__uint_as_float(f2tf(acc[mt][nt][0] + bb.x)),
                                    __uint_as_float(f2tf(acc[mt][nt][1] + bb.y)));
            float2 v1 = make_float2(__uint_as_float(f2tf(acc[mt][nt][2] + bb.x)),
                                    __uint_as_float(f2tf(acc[mt][nt][3] + bb.y)));
            *(float2*)&out[(size_t)row * C_DIM + col] = v0;
            *(float2*)&out[(size_t)(row + 8) * C_DIM + col] = v1;
        }
    }
}

// ============================================================================
// Flash attention, H=1, d=512. BM=BN=64. ROUND-1 pipeline skeleton (double-
// buffered K/V chunks, issue-before-wait, two syncs per chunk) + cheap
// operands: Q packed in A-fragment layout (LDS.128), no CVTs in mainloop.
// 256 threads, warps 4(rows) x 2(cols).
// ============================================================================
#define KV_STRIDE 68
#define Q_FLOATS  (64 * 512)   // packed: [c8][ks8][wr4][lane32][4]
#define SMEM_FLOATS (Q_FLOATS + 2 * 64 * KV_STRIDE + 64 * KV_STRIDE + 3 * 64)

__global__ __launch_bounds__(256, 1) void attn_kernel(float* __restrict__ out)
{
    extern __shared__ float sm[];
    float* Qs     = sm;                                  // packed Q, 128KB
    float* KVb    = sm + Q_FLOATS;                       // [2][64][68]
    float* Ps     = KVb + 2 * 64 * KV_STRIDE;            // [64][68]
    float* row_m  = Ps + 64 * KV_STRIDE;
    float* row_l  = row_m + 64;
    float* row_al = row_l + 64;

    const int bid = blockIdx.x;
    const int b = bid >> 6;
    const int j = bid & 63;
    const int qt = (j & 1) ? (j >> 1) : (63 - (j >> 1));  // zig-zag balance

    const float* Qg = g_Qp + ((size_t)b * T_DIM + (size_t)qt * 64) * C_DIM;
    const float* Kg = g_Kp + (size_t)b * T_DIM * C_DIM;
    const float* Vg = g_Vp + (size_t)b * T_DIM * C_DIM;

    const int tid = threadIdx.x, lane = tid & 31, wid = tid >> 5;
    const int wr = wid >> 1, wc = wid & 1;
    const int lh = lane >> 2, kk3 = lane & 3;
    const int nbase = wc * 32 + lh;

    // ---- pack Q into A-fragment-major layout:
    //   float idx = (((c*8+ks)*4 + wr)*32 + lane)*4 + (half_k*2 + half_r)
    {
        const float4* Qg4 = (const float4*)Qg;
#pragma unroll 4
        for (int i = tid; i < 64 * 128; i += 256) {
            int row = i & 63, d4 = i >> 6;
            float4 qv = Qg4[(size_t)row * 128 + d4];
            int c = d4 >> 4, dl4 = d4 & 15;
            int ks = dl4 >> 1, half_k = dl4 & 1;
            int wrq = row >> 4, rl = row & 7, half_r = (row >> 3) & 1;
            float* dst = Qs + ((((c * 8 + ks) * 4 + wrq) * 32 + rl * 4) << 2)
                            + half_k * 2 + half_r;
            dst[0] = qv.x; dst[4] = qv.y; dst[8] = qv.z; dst[12] = qv.w;
        }
    }
    if (tid < 64) { row_m[tid] = -CUDART_INF_F; row_l[tid] = 0.f; }

    float o[8][4][4];
#pragma unroll
    for (int c = 0; c < 8; c++)
#pragma unroll
        for (int n = 0; n < 4; n++)
#pragma unroll
            for (int e = 0; e < 4; e++) o[c][n][e] = 0.f;

    const float4* Qp4 = (const float4*)Qs;
    const int nkt = qt + 1;

    auto issueKV = [&](int buf, const float* base, int c) {
        float* dst = KVb + buf * 64 * KV_STRIDE;
        for (int i = tid; i < 64 * 16; i += 256) {
            int row = i >> 4, cf = i & 15;
            cp16(&dst[row * KV_STRIDE + cf * 4], base + (size_t)row * C_DIM + c * 64 + cf * 4);
        }
        CP_COMMIT;
    };

    __syncthreads();  // Q pack visible (also covers row_m/row_l init)

    for (int kt = 0; kt < nkt; ++kt) {
        const float* Kt = Kg + (size_t)kt * 64 * C_DIM;
        const float* Vt = Vg + (size_t)kt * 64 * C_DIM;

        // ---------------- S = Q K^T (8 d-chunks, double buffer) ----------------
        float sacc[4][4];
#pragma unroll
        for (int n = 0; n < 4; n++)
#pragma unroll
            for (int e = 0; e < 4; e++) sacc[n][e] = 0.f;

        issueKV(0, Kt, 0);
        for (int c = 0; c < 8; ++c) {
            if (c + 1 < 8) { issueKV((c + 1) & 1, Kt, c + 1); CP_WAIT(1); }
            else           { CP_WAIT(0); }
            __syncthreads();
            const float* kb = KVb + (c & 1) * 64 * KV_STRIDE;
#pragma unroll
            for (int ks = 0; ks < 8; ++ks) {
                float4 aq = Qp4[((c * 8 + ks) * 4 + wr) * 32 + lane];
                uint32_t a0 = __float_as_uint(aq.x), a1 = __float_as_uint(aq.y);
                uint32_t a2 = __float_as_uint(aq.z), a3 = __float_as_uint(aq.w);
#pragma unroll
                for (int nt = 0; nt < 4; ++nt) {
                    const float* bp = kb + (nbase + nt * 8) * KV_STRIDE + ks * 8 + kk3;
                    uint32_t b0 = __float_as_uint(bp[0]);
                    uint32_t b1 = __float_as_uint(bp[4]);
                    MMA_TF32(sacc[nt], a0, a1, a2, a3, b0, b1);
                }
            }
            __syncthreads();
        }

        // ---------------- mask (diagonal) + store S ----------------
        const bool diag = (kt == qt);
        {
            int r0 = wr * 16 + lh;
#pragma unroll
            for (int nt = 0; nt < 4; ++nt) {
                int c0 = wc * 32 + nt * 8 + 2 * kk3;
                float s0 = sacc[nt][0], s1 = sacc[nt][1], s2 = sacc[nt][2], s3 = sacc[nt][3];
                if (diag) {
                    if (c0     > r0)     s0 = -1e30f;
                    if (c0 + 1 > r0)     s1 = -1e30f;
                    if (c0     > r0 + 8) s2 = -1e30f;
                    if (c0 + 1 > r0 + 8) s3 = -1e30f;
                }
                *(float2*)&Ps[r0 * KV_STRIDE + c0]       = make_float2(s0, s1);
                *(float2*)&Ps[(r0 + 8) * KV_STRIDE + c0] = make_float2(s2, s3);
            }
        }
        __syncthreads();

        issueKV(0, Vt, 0);  // prefetch V chunk 0, overlapped with softmax

        // ---------------- online softmax ----------------
        {
            int row = tid >> 2, seg = tid & 3;
            float* pr = Ps + row * KV_STRIDE + seg * 16;
            float vloc[16];
            float mx = -CUDART_INF_F;
#pragma unroll
            for (int i = 0; i < 16; i++) { vloc[i] = pr[i] * ATTN_SCALE; mx = fmaxf(mx, vloc[i]); }
            mx = fmaxf(mx, __shfl_xor_sync(0xffffffffu, mx, 1));
            mx = fmaxf(mx, __shfl_xor_sync(0xffffffffu, mx, 2));
            float mold = row_m[row];
            float mnew = fmaxf(mold, mx);
            float sum = 0.f;
#pragma unroll
            for (int i = 0; i < 16; i++) {
                float p = __expf(vloc[i] - mnew);
                pr[i] = __uint_as_float(f2tf(p));   // pre-rounded for PV MMA
                sum += p;
            }
            sum += __shfl_xor_sync(0xffffffffu, sum, 1);
            sum += __shfl_xor_sync(0xffffffffu, sum, 2);
            if (seg == 0) {
                float alpha = __expf(mold - mnew);
                row_al[row] = alpha;
                row_l[row] = row_l[row] * alpha + sum;
                row_m[row] = mnew;
            }
        }
        __syncthreads();

        // ---------------- rescale O, cache P fragments ----------------
        {
            int r0 = wr * 16 + lh;
            float al0 = row_al[r0], al1 = row_al[r0 + 8];
#pragma unroll
            for (int c = 0; c < 8; c++)
#pragma unroll
                for (int nt = 0; nt < 4; nt++) {
                    o[c][nt][0] *= al0; o[c][nt][1] *= al0;
                    o[c][nt][2] *= al1; o[c][nt][3] *= al1;
                }
        }
        uint32_t pa[8][4];
        {
            int r0 = wr * 16 + lh;
#pragma unroll
            for (int ks = 0; ks < 8; ks++) {
                int kk = ks * 8 + kk3;
                pa[ks][0] = __float_as_uint(Ps[r0 * KV_STRIDE + kk]);
                pa[ks][1] = __float_as_uint(Ps[(r0 + 8) * KV_STRIDE + kk]);
                pa[ks][2] = __float_as_uint(Ps[r0 * KV_STRIDE + kk + 4]);
                pa[ks][3] = __float_as_uint(Ps[(r0 + 8) * KV_STRIDE + kk + 4]);
            }
        }

        // ---------------- O += P V (8 d-chunks, double buffer) ----------------
#pragma unroll 1
        for (int c = 0; c < 8; ++c) {
            if (c + 1 < 8) { issueKV((c + 1) & 1, Vt, c + 1); CP_WAIT(1); }
            else           { CP_WAIT(0); }
            __syncthreads();
            const float* vb = KVb + (c & 1) * 64 * KV_STRIDE;
#pragma unroll
            for (int ks = 0; ks < 8; ++ks) {
#pragma unroll
                for (int nt = 0; nt < 4; ++nt) {
                    const float* vp = vb + (ks * 8 + kk3) * KV_STRIDE + nbase + nt * 8;
                    uint32_t b0 = __float_as_uint(vp[0]);
                    uint32_t b1 = __float_as_uint(vp[4 * KV_STRIDE]);
                    MMA_TF32(o[c][nt], pa[ks][0], pa[ks][1], pa[ks][2], pa[ks][3], b0, b1);
                }
            }
            __syncthreads();
        }
    }

    // ---------------- epilogue: O / l -> out ----------------
    {
        int r0 = wr * 16 + lh;
        float inv0 = 1.f / row_l[r0];
        float inv1 = 1.f / row_l[r0 + 8];
        float* og = out + ((size_t)b * T_DIM + (size_t)qt * 64) * C_DIM;
#pragma unroll
        for (int c = 0; c < 8; c++) {
#pragma unroll
            for (int nt = 0; nt < 4; nt++) {
                int col = c * 64 + wc * 32 + nt * 8 + 2 * kk3;
                *(float2*)&og[(size_t)r0 * C_DIM + col] =
                    make_float2(o[c][nt][0] * inv0, o[c][nt][1] * inv0);
                *(float2*)&og[(size_t)(r0 + 8) * C_DIM + col] =
                    make_float2(o[c][nt][2] * inv1, o[c][nt][3] * inv1);
            }
        }
    }
}

// ============================================================================
// Launch
// ============================================================================
extern "C" void kernel_launch(void* const* d_in, const int* in_sizes, int n_in,
                              void* d_out, int out_size)
{
    const float* q  = (const float*)d_in[0];
    const float* k  = (const float*)d_in[1];
    const float* v  = (const float*)d_in[2];
    const float* Wq = (const float*)d_in[3];
    const float* bq = (const float*)d_in[4];
    const float* Wk = (const float*)d_in[5];
    const float* bk = (const float*)d_in[6];
    const float* Wv = (const float*)d_in[7];
    const float* bv = (const float*)d_in[8];
    float* out = (float*)d_out;

    cudaFuncSetAttribute(attn_kernel, cudaFuncAttributeMaxDynamicSharedMemorySize,
                         SMEM_FLOATS * (int)sizeof(float));

    dim3 pgrid(16384 / 128, 512 / 64, 3);
    proj_kernel<<<pgrid, 256>>>(q, k, v, Wq, bq, Wk, bk, Wv, bv);

    attn_kernel<<<B_DIM * (T_DIM / 64), 256, SMEM_FLOATS * (int)sizeof(float)>>>(out);
}

// round 4
// speedup vs baseline: 1.0213x; 1.0213x over previous
#include <cuda_runtime.h>
#include <cstdint>
#include <math_constants.h>

#define B_DIM 4
#define T_DIM 4096
#define C_DIM 512
#define ATTN_SCALE 0.044194173824159216f  // 1/sqrt(512)

// Scratch for projected Q/K/V (fp32 values pre-rounded to tf32 precision).
__device__ float g_Qp[B_DIM * T_DIM * C_DIM];
__device__ float g_Kp[B_DIM * T_DIM * C_DIM];
__device__ float g_Vp[B_DIM * T_DIM * C_DIM];

__device__ __forceinline__ uint32_t f2tf(float x) {
    uint32_t u;
    asm("cvt.rna.tf32.f32 %0, %1;" : "=r"(u) : "f"(x));
    return u;
}

__device__ __forceinline__ void cp16(void* s, const void* g) {
    uint32_t sa = (uint32_t)__cvta_generic_to_shared(s);
    asm volatile("cp.async.cg.shared.global [%0], [%1], 16;" :: "r"(sa), "l"(g));
}
#define CP_COMMIT asm volatile("cp.async.commit_group;")
#define CP_WAIT(N) asm volatile("cp.async.wait_group %0;" :: "n"(N))

#define MMA_TF32(d, a0, a1, a2, a3, b0, b1)                                  \
    asm volatile(                                                            \
        "mma.sync.aligned.m16n8k8.row.col.f32.tf32.tf32.f32 "                \
        "{%0,%1,%2,%3},{%4,%5,%6,%7},{%8,%9},{%0,%1,%2,%3};"                 \
        : "+f"((d)[0]), "+f"((d)[1]), "+f"((d)[2]), "+f"((d)[3])             \
        : "r"(a0), "r"(a1), "r"(a2), "r"(a3), "r"(b0), "r"(b1))

// ============================================================================
// Projection GEMM: out[M,N] = x[M,K] @ W[K,N] + b,  M=16384, K=N=512.
// Outputs PRE-ROUNDED to tf32 so the attention mainloop needs no CVTs.
// ============================================================================
__global__ __launch_bounds__(256) void proj_kernel(
    const float* __restrict__ xq, const float* __restrict__ xk, const float* __restrict__ xv,
    const float* __restrict__ Wq, const float* __restrict__ bq,
    const float* __restrict__ Wk, const float* __restrict__ bk,
    const float* __restrict__ Wv, const float* __restrict__ bv)
{
    __shared__ float As[2][128][20];
    __shared__ float Bs[2][16][68];

    const int which = blockIdx.z;
    const float* x    = (which == 0) ? xq : (which == 1) ? xk : xv;
    const float* W    = (which == 0) ? Wq : (which == 1) ? Wk : Wv;
    const float* bias = (which == 0) ? bq : (which == 1) ? bk : bv;
    float* out        = (which == 0) ? g_Qp : (which == 1) ? g_Kp : g_Vp;

    const int m0 = blockIdx.x * 128;
    const int n0 = blockIdx.y * 64;
    const int tid = threadIdx.x, lane = tid & 31, wid = tid >> 5;
    const int wr = wid >> 1, wc = wid & 1;

    float acc[2][4][4];
#pragma unroll
    for (int a = 0; a < 2; a++)
#pragma unroll
        for (int b = 0; b < 4; b++)
#pragma unroll
            for (int c = 0; c < 4; c++) acc[a][b][c] = 0.f;

    auto issue = [&](int buf, int k0) {
#pragma unroll
        for (int j = 0; j < 2; j++) {
            int i = tid + 256 * j;
            int row = i >> 2, cf = i & 3;
            cp16(&As[buf][row][cf * 4], x + (size_t)(m0 + row) * C_DIM + k0 + cf * 4);
        }
        {
            int row = tid >> 4, cf = tid & 15;
            cp16(&Bs[buf][row][cf * 4], W + (size_t)(k0 + row) * C_DIM + n0 + cf * 4);
        }
        CP_COMMIT;
    };

    issue(0, 0);
    for (int kt = 0; kt < 32; ++kt) {
        if (kt + 1 < 32) { issue((kt + 1) & 1, (kt + 1) * 16); CP_WAIT(1); }
        else             { CP_WAIT(0); }
        __syncthreads();
        const int buf = kt & 1;
#pragma unroll
        for (int ks = 0; ks < 2; ++ks) {
            uint32_t afr[2][4];
#pragma unroll
            for (int mt = 0; mt < 2; ++mt) {
                int r = wr * 32 + mt * 16 + (lane >> 2);
                int cc = ks * 8 + (lane & 3);
                afr[mt][0] = f2tf(As[buf][r][cc]);
                afr[mt][1] = f2tf(As[buf][r + 8][cc]);
                afr[mt][2] = f2tf(As[buf][r][cc + 4]);
                afr[mt][3] = f2tf(As[buf][r + 8][cc + 4]);
            }
#pragma unroll
            for (int nt = 0; nt < 4; ++nt) {
                int n = wc * 32 + nt * 8 + (lane >> 2);
                int kk = ks * 8 + (lane & 3);
                uint32_t b0 = f2tf(Bs[buf][kk][n]);
                uint32_t b1 = f2tf(Bs[buf][kk + 4][n]);
                MMA_TF32(acc[0][nt], afr[0][0], afr[0][1], afr[0][2], afr[0][3], b0, b1);
                MMA_TF32(acc[1][nt], afr[1][0], afr[1][1], afr[1][2], afr[1][3], b0, b1);
            }
        }
        __syncthreads();
    }

#pragma unroll
    for (int mt = 0; mt < 2; ++mt) {
        int row = m0 + wr * 32 + mt * 16 + (lane >> 2);
#pragma unroll
        for (int nt = 0; nt < 4; ++nt) {
            int col = n0 + wc * 32 + nt * 8 + 2 * (lane & 3);
            float2 bb = *(const float2*)&bias[col];
            float2 v0 = make_float2(__uint_as_float(f2tf(acc[mt][nt][0] + bb.x)),
                                    __uint_as_float(f2tf(acc[mt][nt][1] + bb.y)));
            float2 v1 = make_float2(__uint_as_float(f2tf(acc[mt][nt][2] + bb.x)),
                                    __uint_as_float(f2tf(acc[mt][nt][3] + bb.y)));
            *(float2*)&out[(size_t)row * C_DIM + col] = v0;
            *(float2*)&out[(size_t)(row + 8) * C_DIM + col] = v1;
        }
    }
}

// ============================================================================
// Flash attention, H=1, d=512. BM=BN=64, 512 THREADS (16 warps, 4/SMSP).
// Warp grid 4(rows) x 4(cols): each warp does 16x16 of S per chunk and owns a
// 16-col-interleaved slice of O. Q resident in smem in A-fragment layout
// (1 LDS.128 per fragment). K/V double-buffered via cp.async, 1 CTA/SM.
// ============================================================================
#define KV_STRIDE 68
#define Q_FLOATS  (64 * 512)   // packed: [c8][ks8][wr4][lane32][4]
#define SMEM_FLOATS (Q_FLOATS + 2 * 64 * KV_STRIDE + 64 * KV_STRIDE + 3 * 64)

__global__ __launch_bounds__(512, 1) void attn_kernel(float* __restrict__ out)
{
    extern __shared__ float sm[];
    float* Qs     = sm;                                  // packed Q, 128KB
    float* KVb    = sm + Q_FLOATS;                       // [2][64][68]
    float* Ps     = KVb + 2 * 64 * KV_STRIDE;            // [64][68]
    float* row_m  = Ps + 64 * KV_STRIDE;
    float* row_l  = row_m + 64;
    float* row_al = row_l + 64;

    const int bid = blockIdx.x;
    const int b = bid >> 6;
    const int j = bid & 63;
    const int qt = (j & 1) ? (j >> 1) : (63 - (j >> 1));  // zig-zag balance

    const float* Qg = g_Qp + ((size_t)b * T_DIM + (size_t)qt * 64) * C_DIM;
    const float* Kg = g_Kp + (size_t)b * T_DIM * C_DIM;
    const float* Vg = g_Vp + (size_t)b * T_DIM * C_DIM;

    const int tid = threadIdx.x, lane = tid & 31, wid = tid >> 5;
    const int wr = wid >> 2, wc = wid & 3;               // 4 x 4 warp grid
    const int lh = lane >> 2, kk3 = lane & 3;
    const int nbase = wc * 16 + lh;

    // ---- pack Q into A-fragment-major layout:
    //   float idx = (((c*8+ks)*4 + wr)*32 + lane)*4 + (half_k*2 + half_r)
    {
        const float4* Qg4 = (const float4*)Qg;
#pragma unroll 2
        for (int i = tid; i < 64 * 128; i += 512) {
            int row = i & 63, d4 = i >> 6;
            float4 qv = Qg4[(size_t)row * 128 + d4];
            int c = d4 >> 4, dl4 = d4 & 15;
            int ks = dl4 >> 1, half_k = dl4 & 1;
            int wrq = row >> 4, rl = row & 7, half_r = (row >> 3) & 1;
            float* dst = Qs + ((((c * 8 + ks) * 4 + wrq) * 32 + rl * 4) << 2)
                            + half_k * 2 + half_r;
            dst[0] = qv.x; dst[4] = qv.y; dst[8] = qv.z; dst[12] = qv.w;
        }
    }
    if (tid < 64) { row_m[tid] = -CUDART_INF_F; row_l[tid] = 0.f; }

    // O: warp (wr,wc) owns rows wr*16..+16, cols {c*64 + wc*16..+16} for c=0..7
    float o[8][2][4];
#pragma unroll
    for (int c = 0; c < 8; c++)
#pragma unroll
        for (int n = 0; n < 2; n++)
#pragma unroll
            for (int e = 0; e < 4; e++) o[c][n][e] = 0.f;

    const float4* Qp4 = (const float4*)Qs;
    const int nkt = qt + 1;

    auto issueKV = [&](int buf, const float* base, int c) {
        float* dst = KVb + buf * 64 * KV_STRIDE;
#pragma unroll
        for (int i2 = 0; i2 < 2; i2++) {
            int i = tid + 512 * i2;
            int row = i >> 4, cf = i & 15;
            cp16(&dst[row * KV_STRIDE + cf * 4], base + (size_t)row * C_DIM + c * 64 + cf * 4);
        }
        CP_COMMIT;
    };

    __syncthreads();  // Q pack + stats init visible

    for (int kt = 0; kt < nkt; ++kt) {
        const float* Kt = Kg + (size_t)kt * 64 * C_DIM;
        const float* Vt = Vg + (size_t)kt * 64 * C_DIM;

        // ---------------- S = Q K^T (8 d-chunks, double buffer) ----------------
        float sacc[2][4];
#pragma unroll
        for (int n = 0; n < 2; n++)
#pragma unroll
            for (int e = 0; e < 4; e++) sacc[n][e] = 0.f;

        issueKV(0, Kt, 0);
#pragma unroll 1
        for (int c = 0; c < 8; ++c) {
            if (c + 1 < 8) { issueKV((c + 1) & 1, Kt, c + 1); CP_WAIT(1); }
            else           { CP_WAIT(0); }
            __syncthreads();
            const float* kb = KVb + (c & 1) * 64 * KV_STRIDE;
#pragma unroll
            for (int ks = 0; ks < 8; ++ks) {
                float4 aq = Qp4[((c * 8 + ks) * 4 + wr) * 32 + lane];
                uint32_t a0 = __float_as_uint(aq.x), a1 = __float_as_uint(aq.y);
                uint32_t a2 = __float_as_uint(aq.z), a3 = __float_as_uint(aq.w);
#pragma unroll
                for (int nt = 0; nt < 2; ++nt) {
                    const float* bp = kb + (nbase + nt * 8) * KV_STRIDE + ks * 8 + kk3;
                    uint32_t b0 = __float_as_uint(bp[0]);
                    uint32_t b1 = __float_as_uint(bp[4]);
                    MMA_TF32(sacc[nt], a0, a1, a2, a3, b0, b1);
                }
            }
            __syncthreads();
        }

        // ---------------- mask (diagonal) + store S ----------------
        const bool diag = (kt == qt);
        {
            int r0 = wr * 16 + lh;
#pragma unroll
            for (int nt = 0; nt < 2; ++nt) {
                int c0 = wc * 16 + nt * 8 + 2 * kk3;
                float s0 = sacc[nt][0], s1 = sacc[nt][1], s2 = sacc[nt][2], s3 = sacc[nt][3];
                if (diag) {
                    if (c0     > r0)     s0 = -1e30f;
                    if (c0 + 1 > r0)     s1 = -1e30f;
                    if (c0     > r0 + 8) s2 = -1e30f;
                    if (c0 + 1 > r0 + 8) s3 = -1e30f;
                }
                *(float2*)&Ps[r0 * KV_STRIDE + c0]       = make_float2(s0, s1);
                *(float2*)&Ps[(r0 + 8) * KV_STRIDE + c0] = make_float2(s2, s3);
            }
        }
        __syncthreads();

        issueKV(0, Vt, 0);  // prefetch V chunk 0, overlapped with softmax

        // ---------------- online softmax (8 threads per row) ----------------
        {
            int row = tid >> 3, seg = tid & 7;
            float* pr = Ps + row * KV_STRIDE + seg * 8;
            float vloc[8];
            float mx = -CUDART_INF_F;
#pragma unroll
            for (int i = 0; i < 8; i++) { vloc[i] = pr[i] * ATTN_SCALE; mx = fmaxf(mx, vloc[i]); }
            mx = fmaxf(mx, __shfl_xor_sync(0xffffffffu, mx, 1));
            mx = fmaxf(mx, __shfl_xor_sync(0xffffffffu, mx, 2));
            mx = fmaxf(mx, __shfl_xor_sync(0xffffffffu, mx, 4));
            float mold = row_m[row];
            float mnew = fmaxf(mold, mx);
            float sum = 0.f;
#pragma unroll
            for (int i = 0; i < 8; i++) {
                float p = __expf(vloc[i] - mnew);
                pr[i] = __uint_as_float(f2tf(p));   // pre-rounded for PV MMA
                sum += p;
            }
            sum += __shfl_xor_sync(0xffffffffu, sum, 1);
            sum += __shfl_xor_sync(0xffffffffu, sum, 2);
            sum += __shfl_xor_sync(0xffffffffu, sum, 4);
            if (seg == 0) {
                float alpha = __expf(mold - mnew);
                row_al[row] = alpha;
                row_l[row] = row_l[row] * alpha + sum;
                row_m[row] = mnew;
            }
        }
        __syncthreads();

        // ---------------- rescale O, cache P fragments ----------------
        {
            int r0 = wr * 16 + lh;
            float al0 = row_al[r0], al1 = row_al[r0 + 8];
#pragma unroll
            for (int c = 0; c < 8; c++)
#pragma unroll
                for (int nt = 0; nt < 2; nt++) {
                    o[c][nt][0] *= al0; o[c][nt][1] *= al0;
                    o[c][nt][2] *= al1; o[c][nt][3] *= al1;
                }
        }
        uint32_t pa[8][4];
        {
            int r0 = wr * 16 + lh;
#pragma unroll
            for (int ks = 0; ks < 8; ks++) {
                int kk = ks * 8 + kk3;
                pa[ks][0] = __float_as_uint(Ps[r0 * KV_STRIDE + kk]);
                pa[ks][1] = __float_as_uint(Ps[(r0 + 8) * KV_STRIDE + kk]);
                pa[ks][2] = __float_as_uint(Ps[r0 * KV_STRIDE + kk + 4]);
                pa[ks][3] = __float_as_uint(Ps[(r0 + 8) * KV_STRIDE + kk + 4]);
            }
        }

        // ---------------- O += P V (8 d-chunks, double buffer) ----------------
#pragma unroll 1
        for (int c = 0; c < 8; ++c) {
            if (c + 1 < 8) { issueKV((c + 1) & 1, Vt, c + 1); CP_WAIT(1); }
            else           { CP_WAIT(0); }
            __syncthreads();
            const float* vb = KVb + (c & 1) * 64 * KV_STRIDE;
#pragma unroll
            for (int ks = 0; ks < 8; ++ks) {
#pragma unroll
                for (int nt = 0; nt < 2; ++nt) {
                    const float* vp = vb + (ks * 8 + kk3) * KV_STRIDE + nbase + nt * 8;
                    uint32_t b0 = __float_as_uint(vp[0]);
                    uint32_t b1 = __float_as_uint(vp[4 * KV_STRIDE]);
                    MMA_TF32(o[c][nt], pa[ks][0], pa[ks][1], pa[ks][2], pa[ks][3], b0, b1);
                }
            }
            __syncthreads();
        }
    }

    // ---------------- epilogue: O / l -> out ----------------
    {
        int r0 = wr * 16 + lh;
        float inv0 = 1.f / row_l[r0];
        float inv1 = 1.f / row_l[r0 + 8];
        float* og = out + ((size_t)b * T_DIM + (size_t)qt * 64) * C_DIM;
#pragma unroll
        for (int c = 0; c < 8; c++) {
#pragma unroll
            for (int nt = 0; nt < 2; nt++) {
                int col = c * 64 + wc * 16 + nt * 8 + 2 * kk3;
                *(float2*)&og[(size_t)r0 * C_DIM + col] =
                    make_float2(o[c][nt][0] * inv0, o[c][nt][1] * inv0);
                *(float2*)&og[(size_t)(r0 + 8) * C_DIM + col] =
                    make_float2(o[c][nt][2] * inv1, o[c][nt][3] * inv1);
            }
        }
    }
}

// ============================================================================
// Launch
// ============================================================================
extern "C" void kernel_launch(void* const* d_in, const int* in_sizes, int n_in,
                              void* d_out, int out_size)
{
    const float* q  = (const float*)d_in[0];
    const float* k  = (const float*)d_in[1];
    const float* v  = (const float*)d_in[2];
    const float* Wq = (const float*)d_in[3];
    const float* bq = (const float*)d_in[4];
    const float* Wk = (const float*)d_in[5];
    const float* bk = (const float*)d_in[6];
    const float* Wv = (const float*)d_in[7];
    const float* bv = (const float*)d_in[8];
    float* out = (float*)d_out;

    cudaFuncSetAttribute(attn_kernel, cudaFuncAttributeMaxDynamicSharedMemorySize,
                         SMEM_FLOATS * (int)sizeof(float));

    dim3 pgrid(16384 / 128, 512 / 64, 3);
    proj_kernel<<<pgrid, 256>>>(q, k, v, Wq, bq, Wk, bk, Wv, bv);

    attn_kernel<<<B_DIM * (T_DIM / 64), 512, SMEM_FLOATS * (int)sizeof(float)>>>(out);
}

// round 6
// speedup vs baseline: 1.4432x; 1.4131x over previous
#include <cuda_runtime.h>
#include <cstdint>
#include <math_constants.h>

#define B_DIM 4
#define T_DIM 4096
#define C_DIM 512
#define ATTN_SCALE 0.044194173824159216f  // 1/sqrt(512)

// Scratch for projected Q/K/V (fp32). __device__ globals per allocation rules.
__device__ float g_Qp[B_DIM * T_DIM * C_DIM];
__device__ float g_Kp[B_DIM * T_DIM * C_DIM];
__device__ float g_Vp[B_DIM * T_DIM * C_DIM];
__device__ float g_Vt[B_DIM * C_DIM * T_DIM];   // V transposed: [b][d][t]

__device__ __forceinline__ uint32_t f2tf(float x) {
    uint32_t u;
    asm("cvt.rna.tf32.f32 %0, %1;" : "=r"(u) : "f"(x));
    return u;
}

__device__ __forceinline__ void cp16(void* s, const void* g) {
    uint32_t sa = (uint32_t)__cvta_generic_to_shared(s);
    asm volatile("cp.async.cg.shared.global [%0], [%1], 16;" :: "r"(sa), "l"(g));
}
#define CP_COMMIT asm volatile("cp.async.commit_group;")
#define CP_WAIT(N) asm volatile("cp.async.wait_group %0;" :: "n"(N))

#define MMA_TF32(d, a0, a1, a2, a3, b0, b1)                                  \
    asm volatile(                                                            \
        "mma.sync.aligned.m16n8k8.row.col.f32.tf32.tf32.f32 "                \
        "{%0,%1,%2,%3},{%4,%5,%6,%7},{%8,%9},{%0,%1,%2,%3};"                 \
        : "+f"((d)[0]), "+f"((d)[1]), "+f"((d)[2]), "+f"((d)[3])             \
        : "r"(a0), "r"(a1), "r"(a2), "r"(a3), "r"(b0), "r"(b1))

// ============================================================================
// Projection GEMM: out[M,N] = x[M,K] @ W[K,N] + b,  M=16384, K=N=512
// z dim selects q/k/v. BM=128, BN=64, BK=16, 256 threads (warps 4x2).
// ============================================================================
__global__ __launch_bounds__(256) void proj_kernel(
    const float* __restrict__ xq, const float* __restrict__ xk, const float* __restrict__ xv,
    const float* __restrict__ Wq, const float* __restrict__ bq,
    const float* __restrict__ Wk, const float* __restrict__ bk,
    const float* __restrict__ Wv, const float* __restrict__ bv)
{
    __shared__ float As[2][128][20];  // pad 16->20 (conflict-free A frags)
    __shared__ float Bs[2][16][68];

    const int which = blockIdx.z;
    const float* x    = (which == 0) ? xq : (which == 1) ? xk : xv;
    const float* W    = (which == 0) ? Wq : (which == 1) ? Wk : Wv;
    const float* bias = (which == 0) ? bq : (which == 1) ? bk : bv;
    float* out        = (which == 0) ? g_Qp : (which == 1) ? g_Kp : g_Vp;

    const int m0 = blockIdx.x * 128;
    const int n0 = blockIdx.y * 64;
    const int tid = threadIdx.x, lane = tid & 31, wid = tid >> 5;
    const int wr = wid >> 1, wc = wid & 1;   // 4 x 2 warp grid

    float acc[2][4][4];
#pragma unroll
    for (int a = 0; a < 2; a++)
#pragma unroll
        for (int b = 0; b < 4; b++)
#pragma unroll
            for (int c = 0; c < 4; c++) acc[a][b][c] = 0.f;

    auto issue = [&](int buf, int k0) {
#pragma unroll
        for (int j = 0; j < 2; j++) {
            int i = tid + 256 * j;
            int row = i >> 2, cf = i & 3;
            cp16(&As[buf][row][cf * 4], x + (size_t)(m0 + row) * C_DIM + k0 + cf * 4);
        }
        {
            int row = tid >> 4, cf = tid & 15;
            cp16(&Bs[buf][row][cf * 4], W + (size_t)(k0 + row) * C_DIM + n0 + cf * 4);
        }
        CP_COMMIT;
    };

    issue(0, 0);
    for (int kt = 0; kt < 32; ++kt) {
        if (kt + 1 < 32) { issue((kt + 1) & 1, (kt + 1) * 16); CP_WAIT(1); }
        else             { CP_WAIT(0); }
        __syncthreads();
        const int buf = kt & 1;
#pragma unroll
        for (int ks = 0; ks < 2; ++ks) {
            uint32_t afr[2][4];
#pragma unroll
            for (int mt = 0; mt < 2; ++mt) {
                int r = wr * 32 + mt * 16 + (lane >> 2);
                int cc = ks * 8 + (lane & 3);
                afr[mt][0] = f2tf(As[buf][r][cc]);
                afr[mt][1] = f2tf(As[buf][r + 8][cc]);
                afr[mt][2] = f2tf(As[buf][r][cc + 4]);
                afr[mt][3] = f2tf(As[buf][r + 8][cc + 4]);
            }
#pragma unroll
            for (int nt = 0; nt < 4; ++nt) {
                int n = wc * 32 + nt * 8 + (lane >> 2);
                int kk = ks * 8 + (lane & 3);
                uint32_t b0 = f2tf(Bs[buf][kk][n]);
                uint32_t b1 = f2tf(Bs[buf][kk + 4][n]);
                MMA_TF32(acc[0][nt], afr[0][0], afr[0][1], afr[0][2], afr[0][3], b0, b1);
                MMA_TF32(acc[1][nt], afr[1][0], afr[1][1], afr[1][2], afr[1][3], b0, b1);
            }
        }
        __syncthreads();
    }

#pragma unroll
    for (int mt = 0; mt < 2; ++mt) {
        int row = m0 + wr * 32 + mt * 16 + (lane >> 2);
#pragma unroll
        for (int nt = 0; nt < 4; ++nt) {
            int col = n0 + wc * 32 + nt * 8 + 2 * (lane & 3);
            float2 bb = *(const float2*)&bias[col];
            float2 v0 = make_float2(acc[mt][nt][0] + bb.x, acc[mt][nt][1] + bb.y);
            float2 v1 = make_float2(acc[mt][nt][2] + bb.x, acc[mt][nt][3] + bb.y);
            *(float2*)&out[(size_t)row * C_DIM + col] = v0;
            *(float2*)&out[(size_t)(row + 8) * C_DIM + col] = v1;
        }
    }
}

// ============================================================================
// V transpose: g_Vt[b][d][t] = g_Vp[b][t][d].  32x32 tiles via smem.
// ============================================================================
__global__ __launch_bounds__(256) void vtrans_kernel()
{
    __shared__ float tile[32][33];
    const int b = blockIdx.z;
    const int t0 = blockIdx.x * 32, c0 = blockIdx.y * 32;
    const float* src = g_Vp + ((size_t)b * T_DIM + t0) * C_DIM + c0;
    float* dst       = g_Vt + ((size_t)b * C_DIM + c0) * T_DIM + t0;
    const int tx = threadIdx.x & 31, ty = threadIdx.x >> 5;  // 32 x 8
#pragma unroll
    for (int r = ty; r < 32; r += 8) tile[r][tx] = src[(size_t)r * C_DIM + tx];
    __syncthreads();
#pragma unroll
    for (int r = ty; r < 32; r += 8) dst[(size_t)r * T_DIM + tx] = tile[tx][r];
}

// ============================================================================
// Flash attention, H=1, d=512. BM=BN=64. Q tile resident in smem (fp32),
// K streamed keys-major, V streamed from TRANSPOSED g_Vt (d-major rows) so
// PV B-fragment loads are bank-conflict-free (same pattern as S-loop).
// Otherwise byte-for-byte the round-1 champion. 256 threads, warps 4x2.
// ============================================================================
#define QS_STRIDE 516
#define KV_STRIDE 68
#define SMEM_FLOATS (64 * QS_STRIDE + 2 * 64 * KV_STRIDE + 64 * KV_STRIDE + 3 * 64)

__global__ __launch_bounds__(256, 1) void attn_kernel(float* __restrict__ out)
{
    extern __shared__ float sm[];
    float* Qs     = sm;                                  // [64][516]
    float* KVb    = sm + 64 * QS_STRIDE;                 // [2][64][68]
    float* Ps     = KVb + 2 * 64 * KV_STRIDE;            // [64][68]
    float* row_m  = Ps + 64 * KV_STRIDE;                 // [64]
    float* row_l  = row_m + 64;                          // [64]
    float* row_al = row_l + 64;                          // [64]

    const int bid = blockIdx.x;
    const int b = bid >> 6;
    const int j = bid & 63;
    const int qt = (j & 1) ? (j >> 1) : (63 - (j >> 1));  // zig-zag load balance

    const float* Qg  = g_Qp + ((size_t)b * T_DIM + (size_t)qt * 64) * C_DIM;
    const float* Kg  = g_Kp + (size_t)b * T_DIM * C_DIM;
    const float* Vtg = g_Vt + (size_t)b * C_DIM * T_DIM;   // [d][t]

    const int tid = threadIdx.x, lane = tid & 31, wid = tid >> 5;
    const int wr = wid >> 1, wc = wid & 1;

    // Q tile: 64 x 512 fp32
    for (int i = tid; i < 64 * 128; i += 256) {
        int row = i >> 7, cf = i & 127;
        cp16(&Qs[row * QS_STRIDE + cf * 4], Qg + (size_t)row * C_DIM + cf * 4);
    }
    CP_COMMIT;
    if (tid < 64) { row_m[tid] = -CUDART_INF_F; row_l[tid] = 0.f; }

    float o[8][4][4];
#pragma unroll
    for (int c = 0; c < 8; c++)
#pragma unroll
        for (int n = 0; n < 4; n++)
#pragma unroll
            for (int e = 0; e < 4; e++) o[c][n][e] = 0.f;

    CP_WAIT(0);
    __syncthreads();

    int kt;

    auto issueK = [&](int buf, const float* base, int c) {
        float* dst = KVb + buf * 64 * KV_STRIDE;
        for (int i = tid; i < 64 * 16; i += 256) {
            int row = i >> 4, cf = i & 15;
            cp16(&dst[row * KV_STRIDE + cf * 4], base + (size_t)row * C_DIM + c * 64 + cf * 4);
        }
        CP_COMMIT;
    };
    // V chunk c: rows = dims c*64..+64 of Vt, cols = keys kt*64..+64
    auto issueV = [&](int buf, int c) {
        float* dst = KVb + buf * 64 * KV_STRIDE;
        for (int i = tid; i < 64 * 16; i += 256) {
            int row = i >> 4, cf = i & 15;
            cp16(&dst[row * KV_STRIDE + cf * 4],
                 Vtg + (size_t)(c * 64 + row) * T_DIM + kt * 64 + cf * 4);
        }
        CP_COMMIT;
    };

    const int nkt = qt + 1;
    for (kt = 0; kt < nkt; ++kt) {
        const float* Kt = Kg + (size_t)kt * 64 * C_DIM;

        // ---------------- S = Q K^T (accumulate over 8 d-chunks) ----------------
        float sacc[4][4];
#pragma unroll
        for (int n = 0; n < 4; n++)
#pragma unroll
            for (int e = 0; e < 4; e++) sacc[n][e] = 0.f;

        issueK(0, Kt, 0);
        for (int c = 0; c < 8; ++c) {
            if (c + 1 < 8) { issueK((c + 1) & 1, Kt, c + 1); CP_WAIT(1); }
            else           { CP_WAIT(0); }
            __syncthreads();
            const float* kb = KVb + (c & 1) * 64 * KV_STRIDE;
#pragma unroll
            for (int ks = 0; ks < 8; ++ks) {
                int r0 = wr * 16 + (lane >> 2);
                int qc = c * 64 + ks * 8 + (lane & 3);
                uint32_t a0 = f2tf(Qs[r0 * QS_STRIDE + qc]);
                uint32_t a1 = f2tf(Qs[(r0 + 8) * QS_STRIDE + qc]);
                uint32_t a2 = f2tf(Qs[r0 * QS_STRIDE + qc + 4]);
                uint32_t a3 = f2tf(Qs[(r0 + 8) * QS_STRIDE + qc + 4]);
#pragma unroll
                for (int nt = 0; nt < 4; ++nt) {
                    int n = wc * 32 + nt * 8 + (lane >> 2);
                    int kk = ks * 8 + (lane & 3);
                    uint32_t b0 = f2tf(kb[n * KV_STRIDE + kk]);
                    uint32_t b1 = f2tf(kb[n * KV_STRIDE + kk + 4]);
                    MMA_TF32(sacc[nt], a0, a1, a2, a3, b0, b1);
                }
            }
            __syncthreads();
        }

        // ---------------- mask (diagonal tile only) + store S ----------------
        const bool diag = (kt == qt);
        {
            int r0 = wr * 16 + (lane >> 2);
#pragma unroll
            for (int nt = 0; nt < 4; ++nt) {
                int c0 = wc * 32 + nt * 8 + 2 * (lane & 3);
                float s0 = sacc[nt][0], s1 = sacc[nt][1], s2 = sacc[nt][2], s3 = sacc[nt][3];
                if (diag) {
                    if (c0     > r0)     s0 = -1e30f;
                    if (c0 + 1 > r0)     s1 = -1e30f;
                    if (c0     > r0 + 8) s2 = -1e30f;
                    if (c0 + 1 > r0 + 8) s3 = -1e30f;
                }
                *(float2*)&Ps[r0 * KV_STRIDE + c0]       = make_float2(s0, s1);
                *(float2*)&Ps[(r0 + 8) * KV_STRIDE + c0] = make_float2(s2, s3);
            }
        }
        __syncthreads();

        issueV(0, 0);  // prefetch V chunk 0, overlapped with softmax

        // ---------------- online softmax (thread t: row t>>2, 16 cols) ----------------
        {
            int row = tid >> 2, seg = tid & 3;
            float* pr = Ps + row * KV_STRIDE + seg * 16;
            float vloc[16];
            float mx = -CUDART_INF_F;
#pragma unroll
            for (int i = 0; i < 16; i++) { vloc[i] = pr[i] * ATTN_SCALE; mx = fmaxf(mx, vloc[i]); }
            mx = fmaxf(mx, __shfl_xor_sync(0xffffffffu, mx, 1));
            mx = fmaxf(mx, __shfl_xor_sync(0xffffffffu, mx, 2));
            float mold = row_m[row];
            float mnew = fmaxf(mold, mx);
            float sum = 0.f;
#pragma unroll
            for (int i = 0; i < 16; i++) { float p = __expf(vloc[i] - mnew); pr[i] = p; sum += p; }
            sum += __shfl_xor_sync(0xffffffffu, sum, 1);
            sum += __shfl_xor_sync(0xffffffffu, sum, 2);
            if (seg == 0) {
                float alpha = __expf(mold - mnew);
                row_al[row] = alpha;
                row_l[row] = row_l[row] * alpha + sum;
                row_m[row] = mnew;
            }
        }
        __syncthreads();

        // ---------------- rescale O, cache P fragments ----------------
        {
            int r0 = wr * 16 + (lane >> 2);
            float al0 = row_al[r0], al1 = row_al[r0 + 8];
#pragma unroll
            for (int c = 0; c < 8; c++)
#pragma unroll
                for (int nt = 0; nt < 4; nt++) {
                    o[c][nt][0] *= al0; o[c][nt][1] *= al0;
                    o[c][nt][2] *= al1; o[c][nt][3] *= al1;
                }
        }
        uint32_t pa[8][4];
        {
            int r0 = wr * 16 + (lane >> 2);
#pragma unroll
            for (int ks = 0; ks < 8; ks++) {
                int kk = ks * 8 + (lane & 3);
                pa[ks][0] = f2tf(Ps[r0 * KV_STRIDE + kk]);
                pa[ks][1] = f2tf(Ps[(r0 + 8) * KV_STRIDE + kk]);
                pa[ks][2] = f2tf(Ps[r0 * KV_STRIDE + kk + 4]);
                pa[ks][3] = f2tf(Ps[(r0 + 8) * KV_STRIDE + kk + 4]);
            }
        }

        // ---------------- O += P V (8 d-chunks; V rows are dims now) ----------------
#pragma unroll
        for (int c = 0; c < 8; ++c) {
            if (c + 1 < 8) { issueV((c + 1) & 1, c + 1); CP_WAIT(1); }
            else           { CP_WAIT(0); }
            __syncthreads();
            const float* vb = KVb + (c & 1) * 64 * KV_STRIDE;
#pragma unroll
            for (int ks = 0; ks < 8; ++ks) {
#pragma unroll
                for (int nt = 0; nt < 4; ++nt) {
                    int n = wc * 32 + nt * 8 + (lane >> 2);       // d-col within chunk
                    int kk = ks * 8 + (lane & 3);                 // key within tile
                    const float* vp = vb + n * KV_STRIDE + kk;    // Vt: row=d, col=key
                    uint32_t b0 = f2tf(vp[0]);
                    uint32_t b1 = f2tf(vp[4]);
                    MMA_TF32(o[c][nt], pa[ks][0], pa[ks][1], pa[ks][2], pa[ks][3], b0, b1);
                }
            }
            __syncthreads();
        }
    }

    // ---------------- epilogue: O / l -> out ----------------
    {
        int r0 = wr * 16 + (lane >> 2);
        float inv0 = 1.f / row_l[r0];
        float inv1 = 1.f / row_l[r0 + 8];
        float* og = out + ((size_t)b * T_DIM + (size_t)qt * 64) * C_DIM;
#pragma unroll
        for (int c = 0; c < 8; c++) {
#pragma unroll
            for (int nt = 0; nt < 4; nt++) {
                int col = c * 64 + wc * 32 + nt * 8 + 2 * (lane & 3);
                *(float2*)&og[(size_t)r0 * C_DIM + col] =
                    make_float2(o[c][nt][0] * inv0, o[c][nt][1] * inv0);
                *(float2*)&og[(size_t)(r0 + 8) * C_DIM + col] =
                    make_float2(o[c][nt][2] * inv1, o[c][nt][3] * inv1);
            }
        }
    }
}

// ============================================================================
// Launch
// ============================================================================
extern "C" void kernel_launch(void* const* d_in, const int* in_sizes, int n_in,
                              void* d_out, int out_size)
{
    const float* q  = (const float*)d_in[0];
    const float* k  = (const float*)d_in[1];
    const float* v  = (const float*)d_in[2];
    const float* Wq = (const float*)d_in[3];
    const float* bq = (const float*)d_in[4];
    const float* Wk = (const float*)d_in[5];
    const float* bk = (const float*)d_in[6];
    const float* Wv = (const float*)d_in[7];
    const float* bv = (const float*)d_in[8];
    float* out = (float*)d_out;

    cudaFuncSetAttribute(attn_kernel, cudaFuncAttributeMaxDynamicSharedMemorySize,
                         SMEM_FLOATS * (int)sizeof(float));

    dim3 pgrid(16384 / 128, 512 / 64, 3);
    proj_kernel<<<pgrid, 256>>>(q, k, v, Wq, bq, Wk, bk, Wv, bv);

    dim3 tgrid(T_DIM / 32, C_DIM / 32, B_DIM);
    vtrans_kernel<<<tgrid, 256>>>();

    attn_kernel<<<B_DIM * (T_DIM / 64), 256, SMEM_FLOATS * (int)sizeof(float)>>>(out);
}

// round 7
// speedup vs baseline: 1.5725x; 1.0896x over previous
#include <cuda_runtime.h>
#include <cuda_fp16.h>
#include <cstdint>
#include <math_constants.h>

#define B_DIM 4
#define T_DIM 4096
#define C_DIM 512
#define ATTN_SCALE 0.044194173824159216f  // 1/sqrt(512)

// Scratch. Q/K projected to fp16 [b][t][d]; V projected fp32 then transposed
// to fp16 [b][d][t].
__device__ __half g_Qh[B_DIM * T_DIM * C_DIM];
__device__ __half g_Kh[B_DIM * T_DIM * C_DIM];
__device__ float  g_Vp[B_DIM * T_DIM * C_DIM];
__device__ __half g_Vth[B_DIM * C_DIM * T_DIM];

__device__ __forceinline__ uint32_t f2tf(float x) {
    uint32_t u;
    asm("cvt.rna.tf32.f32 %0, %1;" : "=r"(u) : "f"(x));
    return u;
}

__device__ __forceinline__ void cp16(void* s, const void* g) {
    uint32_t sa = (uint32_t)__cvta_generic_to_shared(s);
    asm volatile("cp.async.cg.shared.global [%0], [%1], 16;" :: "r"(sa), "l"(g));
}
#define CP_COMMIT asm volatile("cp.async.commit_group;")
#define CP_WAIT(N) asm volatile("cp.async.wait_group %0;" :: "n"(N))

#define MMA_TF32(d, a0, a1, a2, a3, b0, b1)                                  \
    asm volatile(                                                            \
        "mma.sync.aligned.m16n8k8.row.col.f32.tf32.tf32.f32 "                \
        "{%0,%1,%2,%3},{%4,%5,%6,%7},{%8,%9},{%0,%1,%2,%3};"                 \
        : "+f"((d)[0]), "+f"((d)[1]), "+f"((d)[2]), "+f"((d)[3])             \
        : "r"(a0), "r"(a1), "r"(a2), "r"(a3), "r"(b0), "r"(b1))

#define MMA_F16(d, a0, a1, a2, a3, b0, b1)                                   \
    asm volatile(                                                            \
        "mma.sync.aligned.m16n8k16.row.col.f32.f16.f16.f32 "                 \
        "{%0,%1,%2,%3},{%4,%5,%6,%7},{%8,%9},{%0,%1,%2,%3};"                 \
        : "+f"((d)[0]), "+f"((d)[1]), "+f"((d)[2]), "+f"((d)[3])             \
        : "r"(a0), "r"(a1), "r"(a2), "r"(a3), "r"(b0), "r"(b1))

// ============================================================================
// Projection GEMM (TF32 mma.sync): y = x @ W + b, M=16384, K=N=512.
// which 0/1 (Q/K): epilogue writes fp16. which 2 (V): writes fp32 (transposed
// to fp16 by vtrans).
// ============================================================================
__global__ __launch_bounds__(256) void proj_kernel(
    const float* __restrict__ xq, const float* __restrict__ xk, const float* __restrict__ xv,
    const float* __restrict__ Wq, const float* __restrict__ bq,
    const float* __restrict__ Wk, const float* __restrict__ bk,
    const float* __restrict__ Wv, const float* __restrict__ bv)
{
    __shared__ float As[2][128][20];
    __shared__ float Bs[2][16][68];

    const int which = blockIdx.z;
    const float* x    = (which == 0) ? xq : (which == 1) ? xk : xv;
    const float* W    = (which == 0) ? Wq : (which == 1) ? Wk : Wv;
    const float* bias = (which == 0) ? bq : (which == 1) ? bk : bv;

    const int m0 = blockIdx.x * 128;
    const int n0 = blockIdx.y * 64;
    const int tid = threadIdx.x, lane = tid & 31, wid = tid >> 5;
    const int wr = wid >> 1, wc = wid & 1;

    float acc[2][4][4];
#pragma unroll
    for (int a = 0; a < 2; a++)
#pragma unroll
        for (int b = 0; b < 4; b++)
#pragma unroll
            for (int c = 0; c < 4; c++) acc[a][b][c] = 0.f;

    auto issue = [&](int buf, int k0) {
#pragma unroll
        for (int j = 0; j < 2; j++) {
            int i = tid + 256 * j;
            int row = i >> 2, cf = i & 3;
            cp16(&As[buf][row][cf * 4], x + (size_t)(m0 + row) * C_DIM + k0 + cf * 4);
        }
        {
            int row = tid >> 4, cf = tid & 15;
            cp16(&Bs[buf][row][cf * 4], W + (size_t)(k0 + row) * C_DIM + n0 + cf * 4);
        }
        CP_COMMIT;
    };

    issue(0, 0);
    for (int kt = 0; kt < 32; ++kt) {
        if (kt + 1 < 32) { issue((kt + 1) & 1, (kt + 1) * 16); CP_WAIT(1); }
        else             { CP_WAIT(0); }
        __syncthreads();
        const int buf = kt & 1;
#pragma unroll
        for (int ks = 0; ks < 2; ++ks) {
            uint32_t afr[2][4];
#pragma unroll
            for (int mt = 0; mt < 2; ++mt) {
                int r = wr * 32 + mt * 16 + (lane >> 2);
                int cc = ks * 8 + (lane & 3);
                afr[mt][0] = f2tf(As[buf][r][cc]);
                afr[mt][1] = f2tf(As[buf][r + 8][cc]);
                afr[mt][2] = f2tf(As[buf][r][cc + 4]);
                afr[mt][3] = f2tf(As[buf][r + 8][cc + 4]);
            }
#pragma unroll
            for (int nt = 0; nt < 4; ++nt) {
                int n = wc * 32 + nt * 8 + (lane >> 2);
                int kk = ks * 8 + (lane & 3);
                uint32_t b0 = f2tf(Bs[buf][kk][n]);
                uint32_t b1 = f2tf(Bs[buf][kk + 4][n]);
                MMA_TF32(acc[0][nt], afr[0][0], afr[0][1], afr[0][2], afr[0][3], b0, b1);
                MMA_TF32(acc[1][nt], afr[1][0], afr[1][1], afr[1][2], afr[1][3], b0, b1);
            }
        }
        __syncthreads();
    }

#pragma unroll
    for (int mt = 0; mt < 2; ++mt) {
        int row = m0 + wr * 32 + mt * 16 + (lane >> 2);
#pragma unroll
        for (int nt = 0; nt < 4; ++nt) {
            int col = n0 + wc * 32 + nt * 8 + 2 * (lane & 3);
            float2 bb = *(const float2*)&bias[col];
            float v00 = acc[mt][nt][0] + bb.x, v01 = acc[mt][nt][1] + bb.y;
            float v10 = acc[mt][nt][2] + bb.x, v11 = acc[mt][nt][3] + bb.y;
            if (which == 2) {
                *(float2*)&g_Vp[(size_t)row * C_DIM + col]       = make_float2(v00, v01);
                *(float2*)&g_Vp[(size_t)(row + 8) * C_DIM + col] = make_float2(v10, v11);
            } else {
                __half* outp = (which == 0) ? g_Qh : g_Kh;
                *(__half2*)&outp[(size_t)row * C_DIM + col] =
                    __floats2half2_rn(v00, v01);
                *(__half2*)&outp[(size_t)(row + 8) * C_DIM + col] =
                    __floats2half2_rn(v10, v11);
            }
        }
    }
}

// ============================================================================
// V transpose + fp16: g_Vth[b][d][t] = half(g_Vp[b][t][d]). 32x32 tiles.
// ============================================================================
__global__ __launch_bounds__(256) void vtrans_kernel()
{
    __shared__ float tile[32][33];
    const int b = blockIdx.z;
    const int t0 = blockIdx.x * 32, c0 = blockIdx.y * 32;
    const float* src = g_Vp + ((size_t)b * T_DIM + t0) * C_DIM + c0;
    __half* dst      = g_Vth + ((size_t)b * C_DIM + c0) * T_DIM + t0;
    const int tx = threadIdx.x & 31, ty = threadIdx.x >> 5;
#pragma unroll
    for (int r = ty; r < 32; r += 8) tile[r][tx] = src[(size_t)r * C_DIM + tx];
    __syncthreads();
#pragma unroll
    for (int r = ty; r < 32; r += 8)
        dst[(size_t)r * T_DIM + tx] = __float2half_rn(tile[tx][r]);
}

// ============================================================================
// Flash attention, fp16 m16n8k16, H=1, d=512. BM=BN=64. 256 threads, 4x2
// warp grid. Q resident fp16; K/V in 128-d-wide fp16 chunks, double-buffered.
// S accumulated f32; softmax f32 -> P fp16; PV from transposed V (conflict-
// free). O in 128 f32 regs.
// ============================================================================
// smem byte offsets
#define OFF_Q   0
#define Q_ROWB  1040                        // 520 halves per row
#define OFF_KV  (OFF_Q + 64 * Q_ROWB)       // 66560; two 18432B buffers
#define KV_BUFB 18432
#define K_ROWB  272                         // 136 halves (64 keys x 128 d)
#define V_ROWB  144                         // 72 halves (128 d x 64 keys)
#define OFF_SF  (OFF_KV + 2 * KV_BUFB)      // 103424; f32 [64][68]
#define SF_STR  68
#define OFF_PH  (OFF_SF + 64 * 68 * 4)      // 120832; fp16 [64][72]
#define PH_ROWH 72
#define OFF_ST  (OFF_PH + 64 * PH_ROWH * 2) // 130048
#define SMEM_BYTES (OFF_ST + 3 * 64 * 4)    // 130816

__global__ __launch_bounds__(256, 1) void attn_kernel(float* __restrict__ out)
{
    extern __shared__ char sm[];
    const uint32_t* Qs32 = (const uint32_t*)(sm + OFF_Q);
    float* Sf    = (float*)(sm + OFF_SF);
    __half* Ph   = (__half*)(sm + OFF_PH);
    const uint32_t* Ph32 = (const uint32_t*)(sm + OFF_PH);
    float* row_m  = (float*)(sm + OFF_ST);
    float* row_l  = row_m + 64;
    float* row_al = row_l + 64;

    const int bid = blockIdx.x;
    const int b = bid >> 6;
    const int j = bid & 63;
    const int qt = (j & 1) ? (j >> 1) : (63 - (j >> 1));  // zig-zag balance

    const __half* Qg  = g_Qh  + ((size_t)b * T_DIM + (size_t)qt * 64) * C_DIM;
    const __half* Kg  = g_Kh  + (size_t)b * T_DIM * C_DIM;
    const __half* Vtg = g_Vth + (size_t)b * C_DIM * T_DIM;

    const int tid = threadIdx.x, lane = tid & 31, wid = tid >> 5;
    const int wr = wid >> 1, wc = wid & 1;
    const int g = lane >> 2, t = lane & 3;
    const int r0 = wr * 16 + g;

    // Q tile: 64 rows x 512 halves (1024B payload per row, stride 1040B)
    for (int i = tid; i < 4096; i += 256) {
        int row = i >> 6, cf = i & 63;
        cp16(sm + OFF_Q + row * Q_ROWB + cf * 16, Qg + (size_t)row * C_DIM + cf * 8);
    }
    CP_COMMIT;
    if (tid < 64) { row_m[tid] = -CUDART_INF_F; row_l[tid] = 0.f; }

    float o[4][8][4];
#pragma unroll
    for (int c = 0; c < 4; c++)
#pragma unroll
        for (int n = 0; n < 8; n++)
#pragma unroll
            for (int e = 0; e < 4; e++) o[c][n][e] = 0.f;

    CP_WAIT(0);
    __syncthreads();

    int kt;
    // K chunk c: 64 keys x 128 d (d = c*128..+128)
    auto issueK = [&](int buf, int c) {
        char* dst = sm + OFF_KV + buf * KV_BUFB;
        for (int i = tid; i < 1024; i += 256) {
            int row = i >> 4, cf = i & 15;
            cp16(dst + row * K_ROWB + cf * 16,
                 Kg + ((size_t)(kt * 64 + row)) * C_DIM + c * 128 + cf * 8);
        }
        CP_COMMIT;
    };
    // V chunk c: 128 d-rows (d = c*128..+128) x 64 keys
    auto issueV = [&](int buf, int c) {
        char* dst = sm + OFF_KV + buf * KV_BUFB;
        for (int i = tid; i < 1024; i += 256) {
            int row = i >> 3, cf = i & 7;
            cp16(dst + row * V_ROWB + cf * 16,
                 Vtg + ((size_t)(c * 128 + row)) * T_DIM + kt * 64 + cf * 8);
        }
        CP_COMMIT;
    };

    const int nkt = qt + 1;
    for (kt = 0; kt < nkt; ++kt) {

        // ---------------- S = Q K^T (4 chunks of 128 d) ----------------
        float sacc[4][4];
#pragma unroll
        for (int n = 0; n < 4; n++)
#pragma unroll
            for (int e = 0; e < 4; e++) sacc[n][e] = 0.f;

        issueK(0, 0);
#pragma unroll 1
        for (int c = 0; c < 4; ++c) {
            if (c + 1 < 4) { issueK((c + 1) & 1, c + 1); CP_WAIT(1); }
            else           { CP_WAIT(0); }
            __syncthreads();
            const uint32_t* kb = (const uint32_t*)(sm + OFF_KV + (c & 1) * KV_BUFB);
#pragma unroll
            for (int ks = 0; ks < 8; ++ks) {
                int w = c * 64 + ks * 8 + t;          // word index in Q row
                uint32_t a0 = Qs32[r0 * 260 + w];
                uint32_t a1 = Qs32[(r0 + 8) * 260 + w];
                uint32_t a2 = Qs32[r0 * 260 + w + 4];
                uint32_t a3 = Qs32[(r0 + 8) * 260 + w + 4];
#pragma unroll
                for (int nt = 0; nt < 4; ++nt) {
                    int n = wc * 32 + nt * 8 + g;     // key row
                    uint32_t b0 = kb[n * 68 + ks * 8 + t];
                    uint32_t b1 = kb[n * 68 + ks * 8 + t + 4];
                    MMA_F16(sacc[nt], a0, a1, a2, a3, b0, b1);
                }
            }
            __syncthreads();
        }

        // ---------------- mask (diagonal) + store S (f32) ----------------
        const bool diag = (kt == qt);
        {
#pragma unroll
            for (int nt = 0; nt < 4; ++nt) {
                int c0 = wc * 32 + nt * 8 + 2 * t;
                float s0 = sacc[nt][0], s1 = sacc[nt][1], s2 = sacc[nt][2], s3 = sacc[nt][3];
                if (diag) {
                    if (c0     > r0)     s0 = -1e30f;
                    if (c0 + 1 > r0)     s1 = -1e30f;
                    if (c0     > r0 + 8) s2 = -1e30f;
                    if (c0 + 1 > r0 + 8) s3 = -1e30f;
                }
                *(float2*)&Sf[r0 * SF_STR + c0]       = make_float2(s0, s1);
                *(float2*)&Sf[(r0 + 8) * SF_STR + c0] = make_float2(s2, s3);
            }
        }
        __syncthreads();

        issueV(0, 0);  // prefetch V chunk 0, overlapped with softmax

        // ---------------- online softmax -> P fp16 ----------------
        {
            int row = tid >> 2, seg = tid & 3;
            const float* pr = Sf + row * SF_STR + seg * 16;
            __half* ph = Ph + row * PH_ROWH + seg * 16;
            float vloc[16];
            float mx = -CUDART_INF_F;
#pragma unroll
            for (int i = 0; i < 16; i++) { vloc[i] = pr[i] * ATTN_SCALE; mx = fmaxf(mx, vloc[i]); }
            mx = fmaxf(mx, __shfl_xor_sync(0xffffffffu, mx, 1));
            mx = fmaxf(mx, __shfl_xor_sync(0xffffffffu, mx, 2));
            float mold = row_m[row];
            float mnew = fmaxf(mold, mx);
            float sum = 0.f;
#pragma unroll
            for (int i = 0; i < 16; i++) {
                __half hp = __float2half_rn(__expf(vloc[i] - mnew));
                ph[i] = hp;
                sum += __half2float(hp);
            }
            sum += __shfl_xor_sync(0xffffffffu, sum, 1);
            sum += __shfl_xor_sync(0xffffffffu, sum, 2);
            if (seg == 0) {
                float alpha = __expf(mold - mnew);
                row_al[row] = alpha;
                row_l[row] = row_l[row] * alpha + sum;
                row_m[row] = mnew;
            }
        }
        __syncthreads();

        // ---------------- rescale O, cache P fragments ----------------
        {
            float al0 = row_al[r0], al1 = row_al[r0 + 8];
#pragma unroll
            for (int c = 0; c < 4; c++)
#pragma unroll
                for (int nt = 0; nt < 8; nt++) {
                    o[c][nt][0] *= al0; o[c][nt][1] *= al0;
                    o[c][nt][2] *= al1; o[c][nt][3] *= al1;
                }
        }
        uint32_t pa[4][4];
#pragma unroll
        for (int ks = 0; ks < 4; ks++) {
            int w = ks * 8 + t;
            pa[ks][0] = Ph32[r0 * 36 + w];
            pa[ks][1] = Ph32[(r0 + 8) * 36 + w];
            pa[ks][2] = Ph32[r0 * 36 + w + 4];
            pa[ks][3] = Ph32[(r0 + 8) * 36 + w + 4];
        }

        // ---------------- O += P V (4 chunks of 128 d) ----------------
#pragma unroll 1
        for (int c = 0; c < 4; ++c) {
            if (c + 1 < 4) { issueV((c + 1) & 1, c + 1); CP_WAIT(1); }
            else           { CP_WAIT(0); }
            __syncthreads();
            const uint32_t* vb = (const uint32_t*)(sm + OFF_KV + (c & 1) * KV_BUFB);
#pragma unroll
            for (int ks = 0; ks < 4; ++ks) {
#pragma unroll
                for (int nt = 0; nt < 8; ++nt) {
                    int n = wc * 64 + nt * 8 + g;     // d-row within chunk
                    uint32_t b0 = vb[n * 36 + ks * 8 + t];
                    uint32_t b1 = vb[n * 36 + ks * 8 + t + 4];
                    MMA_F16(o[c][nt], pa[ks][0], pa[ks][1], pa[ks][2], pa[ks][3], b0, b1);
                }
            }
            __syncthreads();
        }
    }

    // ---------------- epilogue: O / l -> out ----------------
    {
        float inv0 = 1.f / row_l[r0];
        float inv1 = 1.f / row_l[r0 + 8];
        float* og = out + ((size_t)b * T_DIM + (size_t)qt * 64) * C_DIM;
#pragma unroll
        for (int c = 0; c < 4; c++) {
#pragma unroll
            for (int nt = 0; nt < 8; nt++) {
                int col = c * 128 + wc * 64 + nt * 8 + 2 * t;
                *(float2*)&og[(size_t)r0 * C_DIM + col] =
                    make_float2(o[c][nt][0] * inv0, o[c][nt][1] * inv0);
                *(float2*)&og[(size_t)(r0 + 8) * C_DIM + col] =
                    make_float2(o[c][nt][2] * inv1, o[c][nt][3] * inv1);
            }
        }
    }
}

// ============================================================================
// Launch
// ============================================================================
extern "C" void kernel_launch(void* const* d_in, const int* in_sizes, int n_in,
                              void* d_out, int out_size)
{
    const float* q  = (const float*)d_in[0];
    const float* k  = (const float*)d_in[1];
    const float* v  = (const float*)d_in[2];
    const float* Wq = (const float*)d_in[3];
    const float* bq = (const float*)d_in[4];
    const float* Wk = (const float*)d_in[5];
    const float* bk = (const float*)d_in[6];
    const float* Wv = (const float*)d_in[7];
    const float* bv = (const float*)d_in[8];
    float* out = (float*)d_out;

    cudaFuncSetAttribute(attn_kernel, cudaFuncAttributeMaxDynamicSharedMemorySize,
                         SMEM_BYTES);

    dim3 pgrid(16384 / 128, 512 / 64, 3);
    proj_kernel<<<pgrid, 256>>>(q, k, v, Wq, bq, Wk, bk, Wv, bv);

    dim3 tgrid(T_DIM / 32, C_DIM / 32, B_DIM);
    vtrans_kernel<<<tgrid, 256>>>();

    attn_kernel<<<B_DIM * (T_DIM / 64), 256, SMEM_BYTES>>>(out);
}

// round 8
// speedup vs baseline: 2.4890x; 1.5828x over previous
#include <cuda_runtime.h>
#include <cuda_fp16.h>
#include <cstdint>
#include <math_constants.h>

#define B_DIM 4
#define T_DIM 4096
#define C_DIM 512
#define ATTN_SCALE 0.044194173824159216f  // 1/sqrt(512)

// Scratch. Q/K projected to fp16 [b][t][d]; V projected fp32 then transposed
// to fp16 [b][d][t].
__device__ __half g_Qh[B_DIM * T_DIM * C_DIM];
__device__ __half g_Kh[B_DIM * T_DIM * C_DIM];
__device__ float  g_Vp[B_DIM * T_DIM * C_DIM];
__device__ __half g_Vth[B_DIM * C_DIM * T_DIM];

__device__ __forceinline__ uint32_t f2tf(float x) {
    uint32_t u;
    asm("cvt.rna.tf32.f32 %0, %1;" : "=r"(u) : "f"(x));
    return u;
}

__device__ __forceinline__ void cp16(void* s, const void* g) {
    uint32_t sa = (uint32_t)__cvta_generic_to_shared(s);
    asm volatile("cp.async.cg.shared.global [%0], [%1], 16;" :: "r"(sa), "l"(g));
}
#define CP_COMMIT asm volatile("cp.async.commit_group;")
#define CP_WAIT(N) asm volatile("cp.async.wait_group %0;" :: "n"(N))
__device__ __forceinline__ void cp_wait_dyn0() { asm volatile("cp.async.wait_group 0;"); }

#define MMA_TF32(d, a0, a1, a2, a3, b0, b1)                                  \
    asm volatile(                                                            \
        "mma.sync.aligned.m16n8k8.row.col.f32.tf32.tf32.f32 "                \
        "{%0,%1,%2,%3},{%4,%5,%6,%7},{%8,%9},{%0,%1,%2,%3};"                 \
        : "+f"((d)[0]), "+f"((d)[1]), "+f"((d)[2]), "+f"((d)[3])             \
        : "r"(a0), "r"(a1), "r"(a2), "r"(a3), "r"(b0), "r"(b1))

#define MMA_F16(d, a0, a1, a2, a3, b0, b1)                                   \
    asm volatile(                                                            \
        "mma.sync.aligned.m16n8k16.row.col.f32.f16.f16.f32 "                 \
        "{%0,%1,%2,%3},{%4,%5,%6,%7},{%8,%9},{%0,%1,%2,%3};"                 \
        : "+f"((d)[0]), "+f"((d)[1]), "+f"((d)[2]), "+f"((d)[3])             \
        : "r"(a0), "r"(a1), "r"(a2), "r"(a3), "r"(b0), "r"(b1))

// ============================================================================
// Projection GEMM (TF32 mma.sync): y = x @ W + b, M=16384, K=N=512.
// which 0/1 (Q/K): fp16 epilogue. which 2 (V): fp32 (transposed by vtrans).
// ============================================================================
__global__ __launch_bounds__(256) void proj_kernel(
    const float* __restrict__ xq, const float* __restrict__ xk, const float* __restrict__ xv,
    const float* __restrict__ Wq, const float* __restrict__ bq,
    const float* __restrict__ Wk, const float* __restrict__ bk,
    const float* __restrict__ Wv, const float* __restrict__ bv)
{
    __shared__ float As[2][128][20];
    __shared__ float Bs[2][16][68];

    const int which = blockIdx.z;
    const float* x    = (which == 0) ? xq : (which == 1) ? xk : xv;
    const float* W    = (which == 0) ? Wq : (which == 1) ? Wk : Wv;
    const float* bias = (which == 0) ? bq : (which == 1) ? bk : bv;

    const int m0 = blockIdx.x * 128;
    const int n0 = blockIdx.y * 64;
    const int tid = threadIdx.x, lane = tid & 31, wid = tid >> 5;
    const int wr = wid >> 1, wc = wid & 1;

    float acc[2][4][4];
#pragma unroll
    for (int a = 0; a < 2; a++)
#pragma unroll
        for (int b = 0; b < 4; b++)
#pragma unroll
            for (int c = 0; c < 4; c++) acc[a][b][c] = 0.f;

    auto issue = [&](int buf, int k0) {
#pragma unroll
        for (int j = 0; j < 2; j++) {
            int i = tid + 256 * j;
            int row = i >> 2, cf = i & 3;
            cp16(&As[buf][row][cf * 4], x + (size_t)(m0 + row) * C_DIM + k0 + cf * 4);
        }
        {
            int row = tid >> 4, cf = tid & 15;
            cp16(&Bs[buf][row][cf * 4], W + (size_t)(k0 + row) * C_DIM + n0 + cf * 4);
        }
        CP_COMMIT;
    };

    issue(0, 0);
    for (int kt = 0; kt < 32; ++kt) {
        if (kt + 1 < 32) { issue((kt + 1) & 1, (kt + 1) * 16); CP_WAIT(1); }
        else             { CP_WAIT(0); }
        __syncthreads();
        const int buf = kt & 1;
#pragma unroll
        for (int ks = 0; ks < 2; ++ks) {
            uint32_t afr[2][4];
#pragma unroll
            for (int mt = 0; mt < 2; ++mt) {
                int r = wr * 32 + mt * 16 + (lane >> 2);
                int cc = ks * 8 + (lane & 3);
                afr[mt][0] = f2tf(As[buf][r][cc]);
                afr[mt][1] = f2tf(As[buf][r + 8][cc]);
                afr[mt][2] = f2tf(As[buf][r][cc + 4]);
                afr[mt][3] = f2tf(As[buf][r + 8][cc + 4]);
            }
#pragma unroll
            for (int nt = 0; nt < 4; ++nt) {
                int n = wc * 32 + nt * 8 + (lane >> 2);
                int kk = ks * 8 + (lane & 3);
                uint32_t b0 = f2tf(Bs[buf][kk][n]);
                uint32_t b1 = f2tf(Bs[buf][kk + 4][n]);
                MMA_TF32(acc[0][nt], afr[0][0], afr[0][1], afr[0][2], afr[0][3], b0, b1);
                MMA_TF32(acc[1][nt], afr[1][0], afr[1][1], afr[1][2], afr[1][3], b0, b1);
            }
        }
        __syncthreads();
    }

#pragma unroll
    for (int mt = 0; mt < 2; ++mt) {
        int row = m0 + wr * 32 + mt * 16 + (lane >> 2);
#pragma unroll
        for (int nt = 0; nt < 4; ++nt) {
            int col = n0 + wc * 32 + nt * 8 + 2 * (lane & 3);
            float2 bb = *(const float2*)&bias[col];
            float v00 = acc[mt][nt][0] + bb.x, v01 = acc[mt][nt][1] + bb.y;
            float v10 = acc[mt][nt][2] + bb.x, v11 = acc[mt][nt][3] + bb.y;
            if (which == 2) {
                *(float2*)&g_Vp[(size_t)row * C_DIM + col]       = make_float2(v00, v01);
                *(float2*)&g_Vp[(size_t)(row + 8) * C_DIM + col] = make_float2(v10, v11);
            } else {
                __half* outp = (which == 0) ? g_Qh : g_Kh;
                *(__half2*)&outp[(size_t)row * C_DIM + col] =
                    __floats2half2_rn(v00, v01);
                *(__half2*)&outp[(size_t)(row + 8) * C_DIM + col] =
                    __floats2half2_rn(v10, v11);
            }
        }
    }
}

// ============================================================================
// V transpose + fp16: g_Vth[b][d][t] = half(g_Vp[b][t][d]). 32x32 tiles.
// ============================================================================
__global__ __launch_bounds__(256) void vtrans_kernel()
{
    __shared__ float tile[32][33];
    const int b = blockIdx.z;
    const int t0 = blockIdx.x * 32, c0 = blockIdx.y * 32;
    const float* src = g_Vp + ((size_t)b * T_DIM + t0) * C_DIM + c0;
    __half* dst      = g_Vth + ((size_t)b * C_DIM + c0) * T_DIM + t0;
    const int tx = threadIdx.x & 31, ty = threadIdx.x >> 5;
#pragma unroll
    for (int r = ty; r < 32; r += 8) tile[r][tx] = src[(size_t)r * C_DIM + tx];
    __syncthreads();
#pragma unroll
    for (int r = ty; r < 32; r += 8)
        dst[(size_t)r * T_DIM + tx] = __float2half_rn(tile[tx][r]);
}

// ============================================================================
// Flash attention, fp16 m16n8k16, full-d tiles (NO chunking). BM=BN=64,
// 256 threads, 4x2 warps. Q + full K tile + full V(transposed) tile resident
// in smem; S phase = 128 MMAs with zero internal barriers, PV likewise.
// P (fp16) aliases the S (f32) buffer with a barrier between read and write.
// 5 barriers + 2 cp waits per key tile (was ~12 + 8).
// ============================================================================
#define OFF_Q   0
#define Q_ROWB  1040                          // 520 halves = 260 words (4g+t banks)
#define OFF_K   (OFF_Q + 64 * Q_ROWB)         // 66560
#define K_ROWB  1040
#define OFF_V   (OFF_K + 64 * K_ROWB)         // 133120; 512 rows x 144B
#define V_ROWB  144                           // 72 halves = 36 words (4g+t banks)
#define OFF_SF  (OFF_V + 512 * V_ROWB)        // 206848; f32 [64][68]; P fp16 aliases
#define SF_STR  68
#define PH_ROWH 72                            // 36-word stride for P
#define OFF_ST  (OFF_SF + 64 * SF_STR * 4)    // 224256
#define SMEM_BYTES (OFF_ST + 3 * 64 * 4)      // 225024

__global__ __launch_bounds__(256, 1) void attn_kernel(float* __restrict__ out)
{
    extern __shared__ char sm[];
    const uint32_t* Qs32 = (const uint32_t*)(sm + OFF_Q);
    const uint32_t* Ks32 = (const uint32_t*)(sm + OFF_K);
    const uint32_t* Vs32 = (const uint32_t*)(sm + OFF_V);
    float* Sf    = (float*)(sm + OFF_SF);
    __half* Ph   = (__half*)(sm + OFF_SF);            // alias (barrier-guarded)
    const uint32_t* Ph32 = (const uint32_t*)(sm + OFF_SF);
    float* row_m  = (float*)(sm + OFF_ST);
    float* row_l  = row_m + 64;
    float* row_al = row_l + 64;

    const int bid = blockIdx.x;
    const int b = bid >> 6;
    const int j = bid & 63;
    const int qt = (j & 1) ? (j >> 1) : (63 - (j >> 1));  // zig-zag balance

    const __half* Qg  = g_Qh  + ((size_t)b * T_DIM + (size_t)qt * 64) * C_DIM;
    const __half* Kg  = g_Kh  + (size_t)b * T_DIM * C_DIM;
    const __half* Vtg = g_Vth + (size_t)b * C_DIM * T_DIM;

    const int tid = threadIdx.x, lane = tid & 31, wid = tid >> 5;
    const int wr = wid >> 1, wc = wid & 1;
    const int g = lane >> 2, t = lane & 3;
    const int r0 = wr * 16 + g;

    auto issueK = [&](int ktile) {
#pragma unroll
        for (int r = 0; r < 16; r++) {
            int i = tid + 256 * r;                    // 0..4095
            int row = i >> 6, cf = i & 63;
            cp16(sm + OFF_K + row * K_ROWB + cf * 16,
                 Kg + (size_t)(ktile * 64 + row) * C_DIM + cf * 8);
        }
        CP_COMMIT;
    };
    auto issueV = [&](int ktile) {
#pragma unroll
        for (int r = 0; r < 16; r++) {
            int i = tid + 256 * r;                    // 0..4095
            int row = i >> 3, cf = i & 7;
            cp16(sm + OFF_V + row * V_ROWB + cf * 16,
                 Vtg + (size_t)row * T_DIM + ktile * 64 + cf * 8);
        }
        CP_COMMIT;
    };

    // Prologue: Q tile (group 1) + K(0) (group 2)
    for (int i = tid; i < 4096; i += 256) {
        int row = i >> 6, cf = i & 63;
        cp16(sm + OFF_Q + row * Q_ROWB + cf * 16, Qg + (size_t)row * C_DIM + cf * 8);
    }
    CP_COMMIT;
    issueK(0);
    if (tid < 64) { row_m[tid] = -CUDART_INF_F; row_l[tid] = 0.f; }

    float o[4][8][4];
#pragma unroll
    for (int c = 0; c < 4; c++)
#pragma unroll
        for (int n = 0; n < 8; n++)
#pragma unroll
            for (int e = 0; e < 4; e++) o[c][n][e] = 0.f;

    const int nkt = qt + 1;
    for (int kt = 0; kt < nkt; ++kt) {
        // -------- wait K(kt) (+Q on first iter); all PV reads of V are done
        CP_WAIT(0);
        __syncthreads();
        issueV(kt);                     // fills V buffer while S computes

        // ---------------- S = Q K^T : 128 MMAs, no internal barriers --------
        float sacc[4][4];
#pragma unroll
        for (int n = 0; n < 4; n++)
#pragma unroll
            for (int e = 0; e < 4; e++) sacc[n][e] = 0.f;

#pragma unroll 8
        for (int ks = 0; ks < 32; ++ks) {
            int w = ks * 8 + t;
            uint32_t a0 = Qs32[r0 * 260 + w];
            uint32_t a1 = Qs32[(r0 + 8) * 260 + w];
            uint32_t a2 = Qs32[r0 * 260 + w + 4];
            uint32_t a3 = Qs32[(r0 + 8) * 260 + w + 4];
#pragma unroll
            for (int nt = 0; nt < 4; ++nt) {
                int n = wc * 32 + nt * 8 + g;
                uint32_t b0 = Ks32[n * 260 + w];
                uint32_t b1 = Ks32[n * 260 + w + 4];
                MMA_F16(sacc[nt], a0, a1, a2, a3, b0, b1);
            }
        }

        // ---------------- mask (diagonal) + store S (f32) ----------------
        const bool diag = (kt == qt);
#pragma unroll
        for (int nt = 0; nt < 4; ++nt) {
            int c0 = wc * 32 + nt * 8 + 2 * t;
            float s0 = sacc[nt][0], s1 = sacc[nt][1], s2 = sacc[nt][2], s3 = sacc[nt][3];
            if (diag) {
                if (c0     > r0)     s0 = -1e30f;
                if (c0 + 1 > r0)     s1 = -1e30f;
                if (c0     > r0 + 8) s2 = -1e30f;
                if (c0 + 1 > r0 + 8) s3 = -1e30f;
            }
            *(float2*)&Sf[r0 * SF_STR + c0]       = make_float2(s0, s1);
            *(float2*)&Sf[(r0 + 8) * SF_STR + c0] = make_float2(s2, s3);
        }
        __syncthreads();

        if (kt + 1 < nkt) issueK(kt + 1);   // K buffer is free now

        // ---------------- online softmax (P fp16 in-place over Sf) ----------
        {
            int row = tid >> 2, seg = tid & 3;
            const float* pr = Sf + row * SF_STR + seg * 16;
            float vloc[16];
            float mx = -CUDART_INF_F;
#pragma unroll
            for (int i = 0; i < 16; i++) { vloc[i] = pr[i] * ATTN_SCALE; mx = fmaxf(mx, vloc[i]); }
            mx = fmaxf(mx, __shfl_xor_sync(0xffffffffu, mx, 1));
            mx = fmaxf(mx, __shfl_xor_sync(0xffffffffu, mx, 2));
            float mold = row_m[row];
            float mnew = fmaxf(mold, mx);
            __syncthreads();            // ALL f32 reads of Sf complete
            __half* ph = Ph + row * PH_ROWH + seg * 16;
            float sum = 0.f;
#pragma unroll
            for (int i = 0; i < 16; i++) {
                __half hp = __float2half_rn(__expf(vloc[i] - mnew));
                ph[i] = hp;
                sum += __half2float(hp);
            }
            sum += __shfl_xor_sync(0xffffffffu, sum, 1);
            sum += __shfl_xor_sync(0xffffffffu, sum, 2);
            if (seg == 0) {
                float alpha = __expf(mold - mnew);
                row_al[row] = alpha;
                row_l[row] = row_l[row] * alpha + sum;
                row_m[row] = mnew;
            }
        }
        __syncthreads();

        // ---------------- rescale O, cache P fragments ----------------
        {
            float al0 = row_al[r0], al1 = row_al[r0 + 8];
#pragma unroll
            for (int c = 0; c < 4; c++)
#pragma unroll
                for (int nt = 0; nt < 8; nt++) {
                    o[c][nt][0] *= al0; o[c][nt][1] *= al0;
                    o[c][nt][2] *= al1; o[c][nt][3] *= al1;
                }
        }
        uint32_t pa[4][4];
#pragma unroll
        for (int ks = 0; ks < 4; ks++) {
            int w = ks * 8 + t;
            pa[ks][0] = Ph32[r0 * 36 + w];
            pa[ks][1] = Ph32[(r0 + 8) * 36 + w];
            pa[ks][2] = Ph32[r0 * 36 + w + 4];
            pa[ks][3] = Ph32[(r0 + 8) * 36 + w + 4];
        }

        // -------- wait V(kt); K(kt+1) may still be in flight ----------------
        if (kt + 1 < nkt) { CP_WAIT(1); } else { CP_WAIT(0); }
        __syncthreads();

        // ---------------- O += P V : 128 MMAs, no internal barriers ---------
#pragma unroll
        for (int ks = 0; ks < 4; ++ks) {
#pragma unroll
            for (int c = 0; c < 4; ++c) {
#pragma unroll
                for (int nt = 0; nt < 8; ++nt) {
                    int n = c * 128 + wc * 64 + nt * 8 + g;
                    uint32_t b0 = Vs32[n * 36 + ks * 8 + t];
                    uint32_t b1 = Vs32[n * 36 + ks * 8 + t + 4];
                    MMA_F16(o[c][nt], pa[ks][0], pa[ks][1], pa[ks][2], pa[ks][3], b0, b1);
                }
            }
        }
        // no tail barrier: next iter's CP_WAIT(0)+sync precedes any V rewrite
    }

    // ---------------- epilogue: O / l -> out ----------------
    {
        float inv0 = 1.f / row_l[r0];
        float inv1 = 1.f / row_l[r0 + 8];
        float* og = out + ((size_t)b * T_DIM + (size_t)qt * 64) * C_DIM;
#pragma unroll
        for (int c = 0; c < 4; c++) {
#pragma unroll
            for (int nt = 0; nt < 8; nt++) {
                int col = c * 128 + wc * 64 + nt * 8 + 2 * t;
                *(float2*)&og[(size_t)r0 * C_DIM + col] =
                    make_float2(o[c][nt][0] * inv0, o[c][nt][1] * inv0);
                *(float2*)&og[(size_t)(r0 + 8) * C_DIM + col] =
                    make_float2(o[c][nt][2] * inv1, o[c][nt][3] * inv1);
            }
        }
    }
}

// ============================================================================
// Launch
// ============================================================================
extern "C" void kernel_launch(void* const* d_in, const int* in_sizes, int n_in,
                              void* d_out, int out_size)
{
    const float* q  = (const float*)d_in[0];
    const float* k  = (const float*)d_in[1];
    const float* v  = (const float*)d_in[2];
    const float* Wq = (const float*)d_in[3];
    const float* bq = (const float*)d_in[4];
    const float* Wk = (const float*)d_in[5];
    const float* bk = (const float*)d_in[6];
    const float* Wv = (const float*)d_in[7];
    const float* bv = (const float*)d_in[8];
    float* out = (float*)d_out;

    cudaFuncSetAttribute(attn_kernel, cudaFuncAttributeMaxDynamicSharedMemorySize,
                         SMEM_BYTES);

    dim3 pgrid(16384 / 128, 512 / 64, 3);
    proj_kernel<<<pgrid, 256>>>(q, k, v, Wq, bq, Wk, bk, Wv, bv);

    dim3 tgrid(T_DIM / 32, C_DIM / 32, B_DIM);
    vtrans_kernel<<<tgrid, 256>>>();

    attn_kernel<<<B_DIM * (T_DIM / 64), 256, SMEM_BYTES>>>(out);
}

// round 10
// speedup vs baseline: 2.6803x; 1.0769x over previous
#include <cuda_runtime.h>
#include <cuda_fp16.h>
#include <cstdint>
#include <math_constants.h>

#define B_DIM 4
#define T_DIM 4096
#define C_DIM 512
#define ATTN_SCALE 0.044194173824159216f  // 1/sqrt(512)

// Scratch. Q/K projected to fp16 [b][t][d]; V projected fp32 then transposed
// to fp16 [b][d][t].
__device__ __half g_Qh[B_DIM * T_DIM * C_DIM];
__device__ __half g_Kh[B_DIM * T_DIM * C_DIM];
__device__ float  g_Vp[B_DIM * T_DIM * C_DIM];
__device__ __half g_Vth[B_DIM * C_DIM * T_DIM];

__device__ __forceinline__ uint32_t f2tf(float x) {
    uint32_t u;
    asm("cvt.rna.tf32.f32 %0, %1;" : "=r"(u) : "f"(x));
    return u;
}

__device__ __forceinline__ void cp16(void* s, const void* g) {
    uint32_t sa = (uint32_t)__cvta_generic_to_shared(s);
    asm volatile("cp.async.cg.shared.global [%0], [%1], 16;" :: "r"(sa), "l"(g));
}
#define CP_COMMIT asm volatile("cp.async.commit_group;")
#define CP_WAIT(N) asm volatile("cp.async.wait_group %0;" :: "n"(N))

#define MMA_TF32(d, a0, a1, a2, a3, b0, b1)                                  \
    asm volatile(                                                            \
        "mma.sync.aligned.m16n8k8.row.col.f32.tf32.tf32.f32 "                \
        "{%0,%1,%2,%3},{%4,%5,%6,%7},{%8,%9},{%0,%1,%2,%3};"                 \
        : "+f"((d)[0]), "+f"((d)[1]), "+f"((d)[2]), "+f"((d)[3])             \
        : "r"(a0), "r"(a1), "r"(a2), "r"(a3), "r"(b0), "r"(b1))

#define MMA_F16(d, a0, a1, a2, a3, b0, b1)                                   \
    asm volatile(                                                            \
        "mma.sync.aligned.m16n8k16.row.col.f32.f16.f16.f32 "                 \
        "{%0,%1,%2,%3},{%4,%5,%6,%7},{%8,%9},{%0,%1,%2,%3};"                 \
        : "+f"((d)[0]), "+f"((d)[1]), "+f"((d)[2]), "+f"((d)[3])             \
        : "r"(a0), "r"(a1), "r"(a2), "r"(a3), "r"(b0), "r"(b1))

#define LDSM_X4(r0, r1, r2, r3, addr)                                        \
    asm volatile("ldmatrix.sync.aligned.m8n8.x4.shared.b16 {%0,%1,%2,%3}, [%4];" \
        : "=r"(r0), "=r"(r1), "=r"(r2), "=r"(r3) : "r"(addr))

// ============================================================================
// Projection GEMM (TF32 mma.sync): y = x @ W + b, M=16384, K=N=512.
// which 0/1 (Q/K): fp16 epilogue. which 2 (V): fp32 (transposed by vtrans).
// ============================================================================
__global__ __launch_bounds__(256) void proj_kernel(
    const float* __restrict__ xq, const float* __restrict__ xk, const float* __restrict__ xv,
    const float* __restrict__ Wq, const float* __restrict__ bq,
    const float* __restrict__ Wk, const float* __restrict__ bk,
    const float* __restrict__ Wv, const float* __restrict__ bv)
{
    __shared__ float As[2][128][20];
    __shared__ float Bs[2][16][68];

    const int which = blockIdx.z;
    const float* x    = (which == 0) ? xq : (which == 1) ? xk : xv;
    const float* W    = (which == 0) ? Wq : (which == 1) ? Wk : Wv;
    const float* bias = (which == 0) ? bq : (which == 1) ? bk : bv;

    const int m0 = blockIdx.x * 128;
    const int n0 = blockIdx.y * 64;
    const int tid = threadIdx.x, lane = tid & 31, wid = tid >> 5;
    const int wr = wid >> 1, wc = wid & 1;

    float acc[2][4][4];
#pragma unroll
    for (int a = 0; a < 2; a++)
#pragma unroll
        for (int b = 0; b < 4; b++)
#pragma unroll
            for (int c = 0; c < 4; c++) acc[a][b][c] = 0.f;

    auto issue = [&](int buf, int k0) {
#pragma unroll
        for (int j = 0; j < 2; j++) {
            int i = tid + 256 * j;
            int row = i >> 2, cf = i & 3;
            cp16(&As[buf][row][cf * 4], x + (size_t)(m0 + row) * C_DIM + k0 + cf * 4);
        }
        {
            int row = tid >> 4, cf = tid & 15;
            cp16(&Bs[buf][row][cf * 4], W + (size_t)(k0 + row) * C_DIM + n0 + cf * 4);
        }
        CP_COMMIT;
    };

    issue(0, 0);
    for (int kt = 0; kt < 32; ++kt) {
        if (kt + 1 < 32) { issue((kt + 1) & 1, (kt + 1) * 16); CP_WAIT(1); }
        else             { CP_WAIT(0); }
        __syncthreads();
        const int buf = kt & 1;
#pragma unroll
        for (int ks = 0; ks < 2; ++ks) {
            uint32_t afr[2][4];
#pragma unroll
            for (int mt = 0; mt < 2; ++mt) {
                int r = wr * 32 + mt * 16 + (lane >> 2);
                int cc = ks * 8 + (lane & 3);
                afr[mt][0] = f2tf(As[buf][r][cc]);
                afr[mt][1] = f2tf(As[buf][r + 8][cc]);
                afr[mt][2] = f2tf(As[buf][r][cc + 4]);
                afr[mt][3] = f2tf(As[buf][r + 8][cc + 4]);
            }
#pragma unroll
            for (int nt = 0; nt < 4; ++nt) {
                int n = wc * 32 + nt * 8 + (lane >> 2);
                int kk = ks * 8 + (lane & 3);
                uint32_t b0 = f2tf(Bs[buf][kk][n]);
                uint32_t b1 = f2tf(Bs[buf][kk + 4][n]);
                MMA_TF32(acc[0][nt], afr[0][0], afr[0][1], afr[0][2], afr[0][3], b0, b1);
                MMA_TF32(acc[1][nt], afr[1][0], afr[1][1], afr[1][2], afr[1][3], b0, b1);
            }
        }
        __syncthreads();
    }

#pragma unroll
    for (int mt = 0; mt < 2; ++mt) {
        int row = m0 + wr * 32 + mt * 16 + (lane >> 2);
#pragma unroll
        for (int nt = 0; nt < 4; ++nt) {
            int col = n0 + wc * 32 + nt * 8 + 2 * (lane & 3);
            float2 bb = *(const float2*)&bias[col];
            float v00 = acc[mt][nt][0] + bb.x, v01 = acc[mt][nt][1] + bb.y;
            float v10 = acc[mt][nt][2] + bb.x, v11 = acc[mt][nt][3] + bb.y;
            if (which == 2) {
                *(float2*)&g_Vp[(size_t)row * C_DIM + col]       = make_float2(v00, v01);
                *(float2*)&g_Vp[(size_t)(row + 8) * C_DIM + col] = make_float2(v10, v11);
            } else {
                __half* outp = (which == 0) ? g_Qh : g_Kh;
                *(__half2*)&outp[(size_t)row * C_DIM + col] =
                    __floats2half2_rn(v00, v01);
                *(__half2*)&outp[(size_t)(row + 8) * C_DIM + col] =
                    __floats2half2_rn(v10, v11);
            }
        }
    }
}

// ============================================================================
// V transpose + fp16: g_Vth[b][d][t] = half(g_Vp[b][t][d]). 32x32 tiles.
// ============================================================================
__global__ __launch_bounds__(256) void vtrans_kernel()
{
    __shared__ float tile[32][33];
    const int b = blockIdx.z;
    const int t0 = blockIdx.x * 32, c0 = blockIdx.y * 32;
    const float* src = g_Vp + ((size_t)b * T_DIM + t0) * C_DIM + c0;
    __half* dst      = g_Vth + ((size_t)b * C_DIM + c0) * T_DIM + t0;
    const int tx = threadIdx.x & 31, ty = threadIdx.x >> 5;
#pragma unroll
    for (int r = ty; r < 32; r += 8) tile[r][tx] = src[(size_t)r * C_DIM + tx];
    __syncthreads();
#pragma unroll
    for (int r = ty; r < 32; r += 8)
        dst[(size_t)r * T_DIM + tx] = __float2half_rn(tile[tx][r]);
}

// ============================================================================
// Flash attention, fp16 m16n8k16 + ldmatrix.x4 operands, full-d tiles.
// BM=BN=64, 256 threads, 4x2 warps. Identical pipeline to round 8; all
// fragment loads are now ldmatrix.x4 (1 instr per 4 fragments).
// ============================================================================
#define OFF_Q   0
#define Q_ROWB  1040                          // 520 halves (260-word stride)
#define OFF_K   (OFF_Q + 64 * Q_ROWB)         // 66560
#define K_ROWB  1040
#define OFF_V   (OFF_K + 64 * K_ROWB)         // 133120; 512 rows x 144B
#define V_ROWB  144                           // 72 halves (36-word stride)
#define OFF_SF  (OFF_V + 512 * V_ROWB)        // 206848; f32 [64][68]; P fp16 aliases
#define SF_STR  68
#define PH_ROWB 144                           // P: 72 halves per row
#define PH_ROWH 72
#define OFF_ST  (OFF_SF + 64 * SF_STR * 4)    // 224256
#define SMEM_BYTES (OFF_ST + 3 * 64 * 4)      // 225024

__global__ __launch_bounds__(256, 1) void attn_kernel(float* __restrict__ out)
{
    extern __shared__ char sm[];
    float* Sf    = (float*)(sm + OFF_SF);
    __half* Ph   = (__half*)(sm + OFF_SF);            // alias (barrier-guarded)
    float* row_m  = (float*)(sm + OFF_ST);
    float* row_l  = row_m + 64;
    float* row_al = row_l + 64;

    const int bid = blockIdx.x;
    const int b = bid >> 6;
    const int j = bid & 63;
    const int qt = (j & 1) ? (j >> 1) : (63 - (j >> 1));  // zig-zag balance

    const __half* Qg  = g_Qh  + ((size_t)b * T_DIM + (size_t)qt * 64) * C_DIM;
    const __half* Kg  = g_Kh  + (size_t)b * T_DIM * C_DIM;
    const __half* Vtg = g_Vth + (size_t)b * C_DIM * T_DIM;

    const int tid = threadIdx.x, lane = tid & 31, wid = tid >> 5;
    const int wr = wid >> 1, wc = wid & 1;
    const int g = lane >> 2, t = lane & 3;
    const int r0 = wr * 16 + g;

    // ---- ldmatrix per-thread base addresses (shared address space) ----
    const uint32_t smb = (uint32_t)__cvta_generic_to_shared(sm);
    // A-fragment style (Q, P): lanes 0-15 -> rows 0-15 @khalf0; 16-31 -> @khalf8
    const int arow = (lane & 15), akh = (lane >> 4) * 8;
    const uint32_t qA = smb + OFF_Q + (wr * 16 + arow) * Q_ROWB + akh * 2;
    const uint32_t pA = smb + OFF_SF + (wr * 16 + arow) * PH_ROWB + akh * 2;
    // B-fragment style (K, V): lanes 0-7 rows n0.. @kh0; 8-15 same rows @kh8;
    // 16-23 rows n0+8 @kh0; 24-31 rows n0+8 @kh8
    const int brow = ((lane >> 4) << 3) + (lane & 7), bkh = ((lane >> 3) & 1) * 8;
    const uint32_t kB0 = smb + OFF_K + (wc * 32 + brow) * K_ROWB + bkh * 2;
    const uint32_t kB1 = kB0 + 16 * K_ROWB;
    const uint32_t vB  = smb + OFF_V + (wc * 64 + brow) * V_ROWB + bkh * 2;

    auto issueK = [&](int ktile) {
#pragma unroll
        for (int r = 0; r < 16; r++) {
            int i = tid + 256 * r;
            int row = i >> 6, cf = i & 63;
            cp16(sm + OFF_K + row * K_ROWB + cf * 16,
                 Kg + (size_t)(ktile * 64 + row) * C_DIM + cf * 8);
        }
        CP_COMMIT;
    };
    auto issueV = [&](int ktile) {
#pragma unroll
        for (int r = 0; r < 16; r++) {
            int i = tid + 256 * r;
            int row = i >> 3, cf = i & 7;
            cp16(sm + OFF_V + row * V_ROWB + cf * 16,
                 Vtg + (size_t)row * T_DIM + ktile * 64 + cf * 8);
        }
        CP_COMMIT;
    };

    // Prologue: Q tile + K(0)
    for (int i = tid; i < 4096; i += 256) {
        int row = i >> 6, cf = i & 63;
        cp16(sm + OFF_Q + row * Q_ROWB + cf * 16, Qg + (size_t)row * C_DIM + cf * 8);
    }
    CP_COMMIT;
    issueK(0);
    if (tid < 64) { row_m[tid] = -CUDART_INF_F; row_l[tid] = 0.f; }

    float o[4][8][4];
#pragma unroll
    for (int c = 0; c < 4; c++)
#pragma unroll
        for (int n = 0; n < 8; n++)
#pragma unroll
            for (int e = 0; e < 4; e++) o[c][n][e] = 0.f;

    const int nkt = qt + 1;
    for (int kt = 0; kt < nkt; ++kt) {
        // -------- wait K(kt) (+Q first iter); PV reads of V done last iter
        CP_WAIT(0);
        __syncthreads();
        issueV(kt);

        // ---------------- S = Q K^T : 128 MMAs + 96 LDSM ----------------
        float sacc[4][4];
#pragma unroll
        for (int n = 0; n < 4; n++)
#pragma unroll
            for (int e = 0; e < 4; e++) sacc[n][e] = 0.f;

#pragma unroll 8
        for (int ks = 0; ks < 32; ++ks) {
            uint32_t a0, a1, a2, a3, b00, b01, b10, b11, b20, b21, b30, b31;
            LDSM_X4(a0, a1, a2, a3, qA + ks * 32);
            LDSM_X4(b00, b01, b10, b11, kB0 + ks * 32);
            LDSM_X4(b20, b21, b30, b31, kB1 + ks * 32);
            MMA_F16(sacc[0], a0, a1, a2, a3, b00, b01);
            MMA_F16(sacc[1], a0, a1, a2, a3, b10, b11);
            MMA_F16(sacc[2], a0, a1, a2, a3, b20, b21);
            MMA_F16(sacc[3], a0, a1, a2, a3, b30, b31);
        }

        // ---------------- mask (diagonal) + store S (f32) ----------------
        const bool diag = (kt == qt);
#pragma unroll
        for (int nt = 0; nt < 4; ++nt) {
            int c0 = wc * 32 + nt * 8 + 2 * t;
            float s0 = sacc[nt][0], s1 = sacc[nt][1], s2 = sacc[nt][2], s3 = sacc[nt][3];
            if (diag) {
                if (c0     > r0)     s0 = -1e30f;
                if (c0 + 1 > r0)     s1 = -1e30f;
                if (c0     > r0 + 8) s2 = -1e30f;
                if (c0 + 1 > r0 + 8) s3 = -1e30f;
            }
            *(float2*)&Sf[r0 * SF_STR + c0]       = make_float2(s0, s1);
            *(float2*)&Sf[(r0 + 8) * SF_STR + c0] = make_float2(s2, s3);
        }
        __syncthreads();

        if (kt + 1 < nkt) issueK(kt + 1);   // K buffer free now

        // ---------------- online softmax (P fp16 in-place over Sf) ----------
        {
            int row = tid >> 2, seg = tid & 3;
            const float* pr = Sf + row * SF_STR + seg * 16;
            float vloc[16];
            float mx = -CUDART_INF_F;
#pragma unroll
            for (int i = 0; i < 16; i++) { vloc[i] = pr[i] * ATTN_SCALE; mx = fmaxf(mx, vloc[i]); }
            mx = fmaxf(mx, __shfl_xor_sync(0xffffffffu, mx, 1));
            mx = fmaxf(mx, __shfl_xor_sync(0xffffffffu, mx, 2));
            float mold = row_m[row];
            float mnew = fmaxf(mold, mx);
            __syncthreads();            // ALL f32 reads of Sf complete
            __half* ph = Ph + row * PH_ROWH + seg * 16;
            float sum = 0.f;
#pragma unroll
            for (int i = 0; i < 16; i++) {
                __half hp = __float2half_rn(__expf(vloc[i] - mnew));
                ph[i] = hp;
                sum += __half2float(hp);
            }
            sum += __shfl_xor_sync(0xffffffffu, sum, 1);
            sum += __shfl_xor_sync(0xffffffffu, sum, 2);
            if (seg == 0) {
                float alpha = __expf(mold - mnew);
                row_al[row] = alpha;
                row_l[row] = row_l[row] * alpha + sum;
                row_m[row] = mnew;
            }
        }
        __syncthreads();

        // ---------------- rescale O, cache P fragments (4 LDSM) -------------
        {
            float al0 = row_al[r0], al1 = row_al[r0 + 8];
#pragma unroll
            for (int c = 0; c < 4; c++)
#pragma unroll
                for (int nt = 0; nt < 8; nt++) {
                    o[c][nt][0] *= al0; o[c][nt][1] *= al0;
                    o[c][nt][2] *= al1; o[c][nt][3] *= al1;
                }
        }
        uint32_t pa[4][4];
#pragma unroll
        for (int ks = 0; ks < 4; ks++)
            LDSM_X4(pa[ks][0], pa[ks][1], pa[ks][2], pa[ks][3], pA + ks * 32);

        // -------- wait V(kt); K(kt+1) may still be in flight ----------------
        if (kt + 1 < nkt) { CP_WAIT(1); } else { CP_WAIT(0); }
        __syncthreads();

        // ---------------- O += P V : 128 MMAs + 64 LDSM ---------------------
#pragma unroll
        for (int ks = 0; ks < 4; ++ks) {
#pragma unroll
            for (int c = 0; c < 4; ++c) {
#pragma unroll
                for (int vr = 0; vr < 4; ++vr) {
                    uint32_t v0, v1, v2, v3;
                    LDSM_X4(v0, v1, v2, v3,
                            vB + (uint32_t)(c * 128 + vr * 16) * V_ROWB + ks * 32);
                    MMA_F16(o[c][vr * 2],     pa[ks][0], pa[ks][1], pa[ks][2], pa[ks][3], v0, v1);
                    MMA_F16(o[c][vr * 2 + 1], pa[ks][0], pa[ks][1], pa[ks][2], pa[ks][3], v2, v3);
                }
            }
        }
        // no tail barrier: next iter's CP_WAIT(0)+sync precedes any V rewrite
    }

    // ---------------- epilogue: O / l -> out ----------------
    {
        float inv0 = 1.f / row_l[r0];
        float inv1 = 1.f / row_l[r0 + 8];
        float* og = out + ((size_t)b * T_DIM + (size_t)qt * 64) * C_DIM;
#pragma unroll
        for (int c = 0; c < 4; c++) {
#pragma unroll
            for (int nt = 0; nt < 8; nt++) {
                int col = c * 128 + wc * 64 + nt * 8 + 2 * t;
                *(float2*)&og[(size_t)r0 * C_DIM + col] =
                    make_float2(o[c][nt][0] * inv0, o[c][nt][1] * inv0);
                *(float2*)&og[(size_t)(r0 + 8) * C_DIM + col] =
                    make_float2(o[c][nt][2] * inv1, o[c][nt][3] * inv1);
            }
        }
    }
}

// ============================================================================
// Launch
// ============================================================================
extern "C" void kernel_launch(void* const* d_in, const int* in_sizes, int n_in,
                              void* d_out, int out_size)
{
    const float* q  = (const float*)d_in[0];
    const float* k  = (const float*)d_in[1];
    const float* v  = (const float*)d_in[2];
    const float* Wq = (const float*)d_in[3];
    const float* bq = (const float*)d_in[4];
    const float* Wk = (const float*)d_in[5];
    const float* bk = (const float*)d_in[6];
    const float* Wv = (const float*)d_in[7];
    const float* bv = (const float*)d_in[8];
    float* out = (float*)d_out;

    cudaFuncSetAttribute(attn_kernel, cudaFuncAttributeMaxDynamicSharedMemorySize,
                         SMEM_BYTES);

    dim3 pgrid(16384 / 128, 512 / 64, 3);
    proj_kernel<<<pgrid, 256>>>(q, k, v, Wq, bq, Wk, bk, Wv, bv);

    dim3 tgrid(T_DIM / 32, C_DIM / 32, B_DIM);
    vtrans_kernel<<<tgrid, 256>>>();

    attn_kernel<<<B_DIM * (T_DIM / 64), 256, SMEM_BYTES>>>(out);
}

// round 12
// speedup vs baseline: 3.2239x; 1.2028x over previous
#include <cuda_runtime.h>
#include <cuda_fp16.h>
#include <cstdint>
#include <math_constants.h>

#define B_DIM 4
#define T_DIM 4096
#define C_DIM 512
#define NEL   (B_DIM * T_DIM * C_DIM)
// scale * log2(e): Q is pre-multiplied so softmax uses exp2 directly
#define SCALE_L2E (0.044194173824159216f * 1.4426950408889634f)

// Scratch
__device__ __half g_Xh [3 * NEL];                 // fp16 inputs (q,k,v)
__device__ __half g_Wth[3 * C_DIM * C_DIM];       // fp16 W^T [n][k]
__device__ __half g_Qh [NEL];                     // Q proj * scale*log2e
__device__ __half g_Kh [NEL];
__device__ float  g_Vp [NEL];                     // V proj fp32
__device__ __half g_Vth[NEL];                     // V transposed [b][d][t]

__device__ __forceinline__ void cp16(void* s, const void* g) {
    uint32_t sa = (uint32_t)__cvta_generic_to_shared(s);
    asm volatile("cp.async.cg.shared.global [%0], [%1], 16;" :: "r"(sa), "l"(g));
}
#define CP_COMMIT asm volatile("cp.async.commit_group;")
#define CP_WAIT(N) asm volatile("cp.async.wait_group %0;" :: "n"(N))

#define MMA_F16(d, a0, a1, a2, a3, b0, b1)                                   \
    asm volatile(                                                            \
        "mma.sync.aligned.m16n8k16.row.col.f32.f16.f16.f32 "                 \
        "{%0,%1,%2,%3},{%4,%5,%6,%7},{%8,%9},{%0,%1,%2,%3};"                 \
        : "+f"((d)[0]), "+f"((d)[1]), "+f"((d)[2]), "+f"((d)[3])             \
        : "r"(a0), "r"(a1), "r"(a2), "r"(a3), "r"(b0), "r"(b1))

#define LDSM_X4(r0, r1, r2, r3, addr)                                        \
    asm volatile("ldmatrix.sync.aligned.m8n8.x4.shared.b16 {%0,%1,%2,%3}, [%4];" \
        : "=r"(r0), "=r"(r1), "=r"(r2), "=r"(r3) : "r"(addr))

// ============================================================================
// xconv: fp32 -> fp16 elementwise, 3 tensors. 8 floats/thread.
// ============================================================================
__global__ __launch_bounds__(256) void xconv_kernel(
    const float* __restrict__ xq, const float* __restrict__ xk, const float* __restrict__ xv)
{
    const int which = blockIdx.z;
    const float* src = (which == 0) ? xq : (which == 1) ? xk : xv;
    __half* dst = g_Xh + (size_t)which * NEL;
    size_t i = ((size_t)blockIdx.x * 256 + threadIdx.x) * 8;
    float4 f0 = *(const float4*)(src + i);
    float4 f1 = *(const float4*)(src + i + 4);
    __half2 h0 = __floats2half2_rn(f0.x, f0.y);
    __half2 h1 = __floats2half2_rn(f0.z, f0.w);
    __half2 h2 = __floats2half2_rn(f1.x, f1.y);
    __half2 h3 = __floats2half2_rn(f1.z, f1.w);
    uint4 u;
    u.x = *(uint32_t*)&h0; u.y = *(uint32_t*)&h1;
    u.z = *(uint32_t*)&h2; u.w = *(uint32_t*)&h3;
    *(uint4*)(dst + i) = u;
}

// ============================================================================
// wtrans: W [k][n] fp32 -> W^T [n][k] fp16. 32x32 tiles.
// ============================================================================
__global__ __launch_bounds__(256) void wtrans_kernel(
    const float* __restrict__ Wq, const float* __restrict__ Wk, const float* __restrict__ Wv)
{
    __shared__ float tile[32][33];
    const int which = blockIdx.z;
    const float* W = (which == 0) ? Wq : (which == 1) ? Wk : Wv;
    __half* Wt = g_Wth + (size_t)which * C_DIM * C_DIM;
    const int k0 = blockIdx.x * 32, n0 = blockIdx.y * 32;
    const int tx = threadIdx.x & 31, ty = threadIdx.x >> 5;
#pragma unroll
    for (int r = ty; r < 32; r += 8) tile[r][tx] = W[(size_t)(k0 + r) * C_DIM + n0 + tx];
    __syncthreads();
#pragma unroll
    for (int r = ty; r < 32; r += 8)
        Wt[(size_t)(n0 + r) * C_DIM + k0 + tx] = __float2half_rn(tile[tx][r]);
}

// ============================================================================
// proj: y = x @ W + b via fp16 m16n8k16 + ldmatrix. BM=128, BN=64, BK=64.
// 256 threads (4m x 2n warps). which 0: g_Qh (*scale*log2e); 1: g_Kh; 2: g_Vp f32.
// ============================================================================
#define PJ_A(buf)  ((buf) * 18432)            // 128 rows x 144B
#define PJ_B(buf)  (36864 + (buf) * 9216)     // 64 rows x 144B
#define PJ_SMEM    55296
#define PJ_ROWB    144

__global__ __launch_bounds__(256, 1) void proj_kernel(
    const float* __restrict__ bq, const float* __restrict__ bk, const float* __restrict__ bv)
{
    extern __shared__ char sm[];
    const int which = blockIdx.z;
    const __half* xh = g_Xh + (size_t)which * NEL;
    const __half* wt = g_Wth + (size_t)which * C_DIM * C_DIM;
    const float* bias = (which == 0) ? bq : (which == 1) ? bk : bv;

    const int m0 = blockIdx.x * 128;
    const int n0 = blockIdx.y * 64;
    const int tid = threadIdx.x, lane = tid & 31, wid = tid >> 5;
    const int wr = wid >> 1, wc = wid & 1;
    const int g = lane >> 2, t = lane & 3;

    const uint32_t smb = (uint32_t)__cvta_generic_to_shared(sm);
    const int arow = (lane & 15), akh = (lane >> 4) * 8;
    const int brow = ((lane >> 4) << 3) + (lane & 7), bkh = ((lane >> 3) & 1) * 8;

    float acc[2][4][4];
#pragma unroll
    for (int mt = 0; mt < 2; mt++)
#pragma unroll
        for (int nt = 0; nt < 4; nt++)
#pragma unroll
            for (int e = 0; e < 4; e++) acc[mt][nt][e] = 0.f;

    auto issue = [&](int buf, int kt) {
#pragma unroll
        for (int r = 0; r < 4; r++) {             // A: 128 x 64 halves
            int i = tid + 256 * r;
            int row = i >> 3, cf = i & 7;
            cp16(sm + PJ_A(buf) + row * PJ_ROWB + cf * 16,
                 xh + (size_t)(m0 + row) * C_DIM + kt * 64 + cf * 8);
        }
#pragma unroll
        for (int r = 0; r < 2; r++) {             // B: 64 x 64 halves
            int i = tid + 256 * r;
            int row = i >> 3, cf = i & 7;
            cp16(sm + PJ_B(buf) + row * PJ_ROWB + cf * 16,
                 wt + (size_t)(n0 + row) * C_DIM + kt * 64 + cf * 8);
        }
        CP_COMMIT;
    };

    issue(0, 0);
    for (int kt = 0; kt < 8; ++kt) {
        if (kt + 1 < 8) { issue((kt + 1) & 1, kt + 1); CP_WAIT(1); }
        else            { CP_WAIT(0); }
        __syncthreads();
        const int buf = kt & 1;
        const uint32_t aA0 = smb + PJ_A(buf) + (wr * 32 + arow) * PJ_ROWB + akh * 2;
        const uint32_t aA1 = aA0 + 16 * PJ_ROWB;
        const uint32_t bB0 = smb + PJ_B(buf) + (wc * 32 + brow) * PJ_ROWB + bkh * 2;
        const uint32_t bB1 = bB0 + 16 * PJ_ROWB;
#pragma unroll
        for (int kf = 0; kf < 4; ++kf) {
            uint32_t a00, a01, a02, a03, a10, a11, a12, a13;
            uint32_t b00, b01, b10, b11, b20, b21, b30, b31;
            LDSM_X4(a00, a01, a02, a03, aA0 + kf * 32);
            LDSM_X4(a10, a11, a12, a13, aA1 + kf * 32);
            LDSM_X4(b00, b01, b10, b11, bB0 + kf * 32);
            LDSM_X4(b20, b21, b30, b31, bB1 + kf * 32);
            MMA_F16(acc[0][0], a00, a01, a02, a03, b00, b01);
            MMA_F16(acc[0][1], a00, a01, a02, a03, b10, b11);
            MMA_F16(acc[0][2], a00, a01, a02, a03, b20, b21);
            MMA_F16(acc[0][3], a00, a01, a02, a03, b30, b31);
            MMA_F16(acc[1][0], a10, a11, a12, a13, b00, b01);
            MMA_F16(acc[1][1], a10, a11, a12, a13, b10, b11);
            MMA_F16(acc[1][2], a10, a11, a12, a13, b20, b21);
            MMA_F16(acc[1][3], a10, a11, a12, a13, b30, b31);
        }
        __syncthreads();
    }

#pragma unroll
    for (int mt = 0; mt < 2; ++mt) {
        int row = m0 + wr * 32 + mt * 16 + g;
#pragma unroll
        for (int nt = 0; nt < 4; ++nt) {
            int col = n0 + wc * 32 + nt * 8 + 2 * t;
            float2 bb = *(const float2*)&bias[col];
            float v00 = acc[mt][nt][0] + bb.x, v01 = acc[mt][nt][1] + bb.y;
            float v10 = acc[mt][nt][2] + bb.x, v11 = acc[mt][nt][3] + bb.y;
            if (which == 0) {
                *(__half2*)&g_Qh[(size_t)row * C_DIM + col] =
                    __floats2half2_rn(v00 * SCALE_L2E, v01 * SCALE_L2E);
                *(__half2*)&g_Qh[(size_t)(row + 8) * C_DIM + col] =
                    __floats2half2_rn(v10 * SCALE_L2E, v11 * SCALE_L2E);
            } else if (which == 1) {
                *(__half2*)&g_Kh[(size_t)row * C_DIM + col] = __floats2half2_rn(v00, v01);
                *(__half2*)&g_Kh[(size_t)(row + 8) * C_DIM + col] = __floats2half2_rn(v10, v11);
            } else {
                *(float2*)&g_Vp[(size_t)row * C_DIM + col]       = make_float2(v00, v01);
                *(float2*)&g_Vp[(size_t)(row + 8) * C_DIM + col] = make_float2(v10, v11);
            }
        }
    }
}

// ============================================================================
// V transpose + fp16: g_Vth[b][d][t] = half(g_Vp[b][t][d]). 32x32 tiles.
// ============================================================================
__global__ __launch_bounds__(256) void vtrans_kernel()
{
    __shared__ float tile[32][33];
    const int b = blockIdx.z;
    const int t0 = blockIdx.x * 32, c0 = blockIdx.y * 32;
    const float* src = g_Vp + ((size_t)b * T_DIM + t0) * C_DIM + c0;
    __half* dst      = g_Vth + ((size_t)b * C_DIM + c0) * T_DIM + t0;
    const int tx = threadIdx.x & 31, ty = threadIdx.x >> 5;
#pragma unroll
    for (int r = ty; r < 32; r += 8) tile[r][tx] = src[(size_t)r * C_DIM + tx];
    __syncthreads();
#pragma unroll
    for (int r = ty; r < 32; r += 8)
        dst[(size_t)r * T_DIM + tx] = __float2half_rn(tile[tx][r]);
}

// ============================================================================
// Flash attention (round-10 champion structure). fp16 m16n8k16 + ldmatrix.x4,
// full-d tiles, BM=BN=64, 256 threads 4x2 warps. Q pre-scaled by scale*log2e
// so softmax uses exp2f (bare MUFU.EX2).
// ============================================================================
#define OFF_Q   0
#define Q_ROWB  1040
#define OFF_K   (OFF_Q + 64 * Q_ROWB)
#define K_ROWB  1040
#define OFF_V   (OFF_K + 64 * K_ROWB)
#define V_ROWB  144
#define OFF_SF  (OFF_V + 512 * V_ROWB)
#define SF_STR  68
#define PH_ROWB 144
#define PH_ROWH 72
#define OFF_ST  (OFF_SF + 64 * SF_STR * 4)
#define SMEM_BYTES (OFF_ST + 3 * 64 * 4)

__global__ __launch_bounds__(256, 1) void attn_kernel(float* __restrict__ out)
{
    extern __shared__ char sm[];
    float* Sf    = (float*)(sm + OFF_SF);
    __half* Ph   = (__half*)(sm + OFF_SF);            // alias (barrier-guarded)
    float* row_m  = (float*)(sm + OFF_ST);
    float* row_l  = row_m + 64;
    float* row_al = row_l + 64;

    const int bid = blockIdx.x;
    const int b = bid >> 6;
    const int j = bid & 63;
    const int qt = (j & 1) ? (j >> 1) : (63 - (j >> 1));  // zig-zag balance

    const __half* Qg  = g_Qh  + ((size_t)b * T_DIM + (size_t)qt * 64) * C_DIM;
    const __half* Kg  = g_Kh  + (size_t)b * T_DIM * C_DIM;
    const __half* Vtg = g_Vth + (size_t)b * C_DIM * T_DIM;

    const int tid = threadIdx.x, lane = tid & 31, wid = tid >> 5;
    const int wr = wid >> 1, wc = wid & 1;
    const int g = lane >> 2, t = lane & 3;
    const int r0 = wr * 16 + g;

    const uint32_t smb = (uint32_t)__cvta_generic_to_shared(sm);
    const int arow = (lane & 15), akh = (lane >> 4) * 8;
    const uint32_t qA = smb + OFF_Q + (wr * 16 + arow) * Q_ROWB + akh * 2;
    const uint32_t pA = smb + OFF_SF + (wr * 16 + arow) * PH_ROWB + akh * 2;
    const int brow = ((lane >> 4) << 3) + (lane & 7), bkh = ((lane >> 3) & 1) * 8;
    const uint32_t kB0 = smb + OFF_K + (wc * 32 + brow) * K_ROWB + bkh * 2;
    const uint32_t kB1 = kB0 + 16 * K_ROWB;
    const uint32_t vB  = smb + OFF_V + (wc * 64 + brow) * V_ROWB + bkh * 2;

    auto issueK = [&](int ktile) {
#pragma unroll
        for (int r = 0; r < 16; r++) {
            int i = tid + 256 * r;
            int row = i >> 6, cf = i & 63;
            cp16(sm + OFF_K + row * K_ROWB + cf * 16,
                 Kg + (size_t)(ktile * 64 + row) * C_DIM + cf * 8);
        }
        CP_COMMIT;
    };
    auto issueV = [&](int ktile) {
#pragma unroll
        for (int r = 0; r < 16; r++) {
            int i = tid + 256 * r;
            int row = i >> 3, cf = i & 7;
            cp16(sm + OFF_V + row * V_ROWB + cf * 16,
                 Vtg + (size_t)row * T_DIM + ktile * 64 + cf * 8);
        }
        CP_COMMIT;
    };

    for (int i = tid; i < 4096; i += 256) {
        int row = i >> 6, cf = i & 63;
        cp16(sm + OFF_Q + row * Q_ROWB + cf * 16, Qg + (size_t)row * C_DIM + cf * 8);
    }
    CP_COMMIT;
    issueK(0);
    if (tid < 64) { row_m[tid] = -CUDART_INF_F; row_l[tid] = 0.f; }

    float o[4][8][4];
#pragma unroll
    for (int c = 0; c < 4; c++)
#pragma unroll
        for (int n = 0; n < 8; n++)
#pragma unroll
            for (int e = 0; e < 4; e++) o[c][n][e] = 0.f;

    const int nkt = qt + 1;
    for (int kt = 0; kt < nkt; ++kt) {
        CP_WAIT(0);
        __syncthreads();
        issueV(kt);

        // ---------------- S = Q K^T ----------------
        float sacc[4][4];
#pragma unroll
        for (int n = 0; n < 4; n++)
#pragma unroll
            for (int e = 0; e < 4; e++) sacc[n][e] = 0.f;

#pragma unroll 8
        for (int ks = 0; ks < 32; ++ks) {
            uint32_t a0, a1, a2, a3, b00, b01, b10, b11, b20, b21, b30, b31;
            LDSM_X4(a0, a1, a2, a3, qA + ks * 32);
            LDSM_X4(b00, b01, b10, b11, kB0 + ks * 32);
            LDSM_X4(b20, b21, b30, b31, kB1 + ks * 32);
            MMA_F16(sacc[0], a0, a1, a2, a3, b00, b01);
            MMA_F16(sacc[1], a0, a1, a2, a3, b10, b11);
            MMA_F16(sacc[2], a0, a1, a2, a3, b20, b21);
            MMA_F16(sacc[3], a0, a1, a2, a3, b30, b31);
        }

        // ---------------- mask + store S (f32) ----------------
        const bool diag = (kt == qt);
#pragma unroll
        for (int nt = 0; nt < 4; ++nt) {
            int c0 = wc * 32 + nt * 8 + 2 * t;
            float s0 = sacc[nt][0], s1 = sacc[nt][1], s2 = sacc[nt][2], s3 = sacc[nt][3];
            if (diag) {
                if (c0     > r0)     s0 = -1e30f;
                if (c0 + 1 > r0)     s1 = -1e30f;
                if (c0     > r0 + 8) s2 = -1e30f;
                if (c0 + 1 > r0 + 8) s3 = -1e30f;
            }
            *(float2*)&Sf[r0 * SF_STR + c0]       = make_float2(s0, s1);
            *(float2*)&Sf[(r0 + 8) * SF_STR + c0] = make_float2(s2, s3);
        }
        __syncthreads();

        if (kt + 1 < nkt) issueK(kt + 1);

        // ---------------- online softmax (base-2; Q pre-scaled) -------------
        {
            int row = tid >> 2, seg = tid & 3;
            const float* pr = Sf + row * SF_STR + seg * 16;
            float vloc[16];
            float mx = -CUDART_INF_F;
#pragma unroll
            for (int i = 0; i < 16; i++) { vloc[i] = pr[i]; mx = fmaxf(mx, vloc[i]); }
            mx = fmaxf(mx, __shfl_xor_sync(0xffffffffu, mx, 1));
            mx = fmaxf(mx, __shfl_xor_sync(0xffffffffu, mx, 2));
            float mold = row_m[row];
            float mnew = fmaxf(mold, mx);
            __syncthreads();
            __half* ph = Ph + row * PH_ROWH + seg * 16;
            float sum = 0.f;
#pragma unroll
            for (int i = 0; i < 16; i++) {
                __half hp = __float2half_rn(exp2f(vloc[i] - mnew));
                ph[i] = hp;
                sum += __half2float(hp);
            }
            sum += __shfl_xor_sync(0xffffffffu, sum, 1);
            sum += __shfl_xor_sync(0xffffffffu, sum, 2);
            if (seg == 0) {
                float alpha = exp2f(mold - mnew);
                row_al[row] = alpha;
                row_l[row] = row_l[row] * alpha + sum;
                row_m[row] = mnew;
            }
        }
        __syncthreads();

        // ---------------- rescale O, cache P fragments ----------------
        {
            float al0 = row_al[r0], al1 = row_al[r0 + 8];
#pragma unroll
            for (int c = 0; c < 4; c++)
#pragma unroll
                for (int nt = 0; nt < 8; nt++) {
                    o[c][nt][0] *= al0; o[c][nt][1] *= al0;
                    o[c][nt][2] *= al1; o[c][nt][3] *= al1;
                }
        }
        uint32_t pa[4][4];
#pragma unroll
        for (int ks = 0; ks < 4; ks++)
            LDSM_X4(pa[ks][0], pa[ks][1], pa[ks][2], pa[ks][3], pA + ks * 32);

        if (kt + 1 < nkt) { CP_WAIT(1); } else { CP_WAIT(0); }
        __syncthreads();

        // ---------------- O += P V ----------------
#pragma unroll
        for (int ks = 0; ks < 4; ++ks) {
#pragma unroll
            for (int c = 0; c < 4; ++c) {
#pragma unroll
                for (int vr = 0; vr < 4; ++vr) {
                    uint32_t v0, v1, v2, v3;
                    LDSM_X4(v0, v1, v2, v3,
                            vB + (uint32_t)(c * 128 + vr * 16) * V_ROWB + ks * 32);
                    MMA_F16(o[c][vr * 2],     pa[ks][0], pa[ks][1], pa[ks][2], pa[ks][3], v0, v1);
                    MMA_F16(o[c][vr * 2 + 1], pa[ks][0], pa[ks][1], pa[ks][2], pa[ks][3], v2, v3);
                }
            }
        }
    }

    // ---------------- epilogue ----------------
    {
        float inv0 = 1.f / row_l[r0];
        float inv1 = 1.f / row_l[r0 + 8];
        float* og = out + ((size_t)b * T_DIM + (size_t)qt * 64) * C_DIM;
#pragma unroll
        for (int c = 0; c < 4; c++) {
#pragma unroll
            for (int nt = 0; nt < 8; nt++) {
                int col = c * 128 + wc * 64 + nt * 8 + 2 * t;
                *(float2*)&og[(size_t)r0 * C_DIM + col] =
                    make_float2(o[c][nt][0] * inv0, o[c][nt][1] * inv0);
                *(float2*)&og[(size_t)(r0 + 8) * C_DIM + col] =
                    make_float2(o[c][nt][2] * inv1, o[c][nt][3] * inv1);
            }
        }
    }
}

// ============================================================================
// Launch
// ============================================================================
extern "C" void kernel_launch(void* const* d_in, const int* in_sizes, int n_in,
                              void* d_out, int out_size)
{
    const float* q  = (const float*)d_in[0];
    const float* k  = (const float*)d_in[1];
    const float* v  = (const float*)d_in[2];
    const float* Wq = (const float*)d_in[3];
    const float* bq = (const float*)d_in[4];
    const float* Wk = (const float*)d_in[5];
    const float* bk = (const float*)d_in[6];
    const float* Wv = (const float*)d_in[7];
    const float* bv = (const float*)d_in[8];
    float* out = (float*)d_out;

    cudaFuncSetAttribute(proj_kernel, cudaFuncAttributeMaxDynamicSharedMemorySize, PJ_SMEM);
    cudaFuncSetAttribute(attn_kernel, cudaFuncAttributeMaxDynamicSharedMemorySize, SMEM_BYTES);

    dim3 cgrid(NEL / (256 * 8), 1, 3);
    xconv_kernel<<<cgrid, 256>>>(q, k, v);

    dim3 wgrid(C_DIM / 32, C_DIM / 32, 3);
    wtrans_kernel<<<wgrid, 256>>>(Wq, Wk, Wv);

    dim3 pgrid(16384 / 128, 512 / 64, 3);
    proj_kernel<<<pgrid, 256, PJ_SMEM>>>(bq, bk, bv);

    dim3 tgrid(T_DIM / 32, C_DIM / 32, B_DIM);
    vtrans_kernel<<<tgrid, 256>>>();

    attn_kernel<<<B_DIM * (T_DIM / 64), 256, SMEM_BYTES>>>(out);
}